// round 8
// baseline (speedup 1.0000x reference)
#include <cuda_runtime.h>
#include <stdint.h>

#define NN  50000
#define NE  800000
#define FIN 512
#define FH  256
#define FO  128

// ---- scratch: __device__ globals ----
__device__ int   g_is64;
__device__ __align__(16) float g_dinv[NN];
__device__ __align__(16) int   g_cnt [NN];
__device__ __align__(16) int   g_off [NN + 1];
__device__ __align__(16) int   g_fill[NN];
__device__ __align__(16) int   g_csr_src[NE];
__device__ __align__(16) float g_csr_w  [NE];
__device__ __align__(16) float g_h1  [(size_t)NN * FH];
__device__ __align__(16) float g_agg1[(size_t)NN * FH];
__device__ __align__(16) float g_h2  [(size_t)NN * FO];

// ---------------------------------------------------------------------------
// edge dtype detect (parallel) + decode
// ---------------------------------------------------------------------------
__global__ void k_detect(const void* __restrict__ ei) {
    const long long* p = (const long long*)ei;
    int lane = threadIdx.x;
    int bad = 0;
    #pragma unroll 4
    for (int i = lane; i < 2048; i += 32) {
        long long v = p[i];
        if (v < 0 || v >= NN) bad = 1;
    }
    unsigned m = __ballot_sync(0xffffffffu, bad);
    if (lane == 0) g_is64 = (m == 0);
}

__device__ __forceinline__ unsigned eidx(const void* __restrict__ ei, size_t idx) {
    if (g_is64) return (unsigned)((const long long*)ei)[idx];
    return (unsigned)((const int*)ei)[idx];
}

// ---------------------------------------------------------------------------
// degree / normalization / CSR build
// ---------------------------------------------------------------------------
__global__ void k_init() {
    int i = blockIdx.x * blockDim.x + threadIdx.x;
    if (i < NN) { g_cnt[i] = 0; g_fill[i] = 0; }
}

__global__ void k_deg_count(const void* __restrict__ ei) {
    int i = blockIdx.x * blockDim.x + threadIdx.x;
    if (i < NE) {
        unsigned d = eidx(ei, (size_t)NE + i);
        if (d < NN) atomicAdd(&g_cnt[d], 1);
    }
}

__global__ void k_dinv() {
    int i = blockIdx.x * blockDim.x + threadIdx.x;
    if (i < NN) g_dinv[i] = rsqrtf((float)(g_cnt[i] + 1));   // +1 self-loop
}

// single-block exclusive scan of g_cnt -> g_off
__global__ void k_scan() {
    __shared__ int sh[1024];
    __shared__ int carry;
    const int tid = threadIdx.x;
    if (tid == 0) carry = 0;
    __syncthreads();

    for (int base = 0; base < NN; base += 1024) {
        int i = base + tid;
        int v = (i < NN) ? g_cnt[i] : 0;
        sh[tid] = v;
        __syncthreads();
        for (int ofs = 1; ofs < 1024; ofs <<= 1) {
            int t = (tid >= ofs) ? sh[tid - ofs] : 0;
            __syncthreads();
            sh[tid] += t;
            __syncthreads();
        }
        if (i < NN) g_off[i] = carry + sh[tid] - v;
        __syncthreads();
        if (tid == 1023) carry += sh[1023];
        __syncthreads();
    }
    if (tid == 0) g_off[NN] = carry;
}

__global__ void k_fill(const void* __restrict__ ei) {
    int i = blockIdx.x * blockDim.x + threadIdx.x;
    if (i < NE) {
        unsigned s = eidx(ei, i);
        unsigned d = eidx(ei, (size_t)NE + i);
        if (s < NN && d < NN) {
            int pos = g_off[d] + atomicAdd(&g_fill[d], 1);
            if (pos < NE) {
                g_csr_src[pos] = (int)s;
                g_csr_w[pos]   = g_dinv[s] * g_dinv[d];
            }
        }
    }
}

// ---------------------------------------------------------------------------
// fp32 SGEMM v3: C = A[M,K] @ B[K,N]; BM=BN=128, BK=16, 256 thr, 8x8 microtile
// double-buffered smem with register staging (LDG next || FMA current).
// layer 0: A = x (param), C = g_h1 ;  layer 1: A = g_agg1, C = g_h2
// ---------------------------------------------------------------------------
#define SPAD 132   // 128 + 4 pad; rows stay 16B-aligned (132*4 = 528)

__global__ void __launch_bounds__(256, 2)
sgemm128(const float* __restrict__ Aext, const float* __restrict__ B,
         int layer, int M, int N, int K) {
    const float* A = (layer == 0) ? Aext : (const float*)g_agg1;
    float*       C = (layer == 0) ? g_h1 : g_h2;

    __shared__ float As[2][16][SPAD];   // [buf][k][m]
    __shared__ float Bs[2][16][SPAD];   // [buf][k][n]

    const int tid = threadIdx.x;
    const int tx  = tid & 15;           // n micro
    const int ty  = tid >> 4;           // m micro
    const int row0 = blockIdx.y * 128;
    const int col0 = blockIdx.x * 128;

    // per-thread load coordinates (2 float4 each for A and B)
    const int ar0 = (tid * 2)     >> 3, ak0 = ((tid * 2)     & 7) ? 4 : 0; // see below
    // simpler: idx-based like R7
    float4 a_reg[2], b_reg[2];

    auto ldg_tile = [&](int k0) {
        #pragma unroll
        for (int i = 0; i < 2; i++) {
            int idx = tid + i * 256;            // 0..511
            int r  = idx >> 2;                  // 0..127
            int kq = idx & 3;                   // float4 within k
            int gr = row0 + r;
            a_reg[i] = (gr < M) ? *(const float4*)&A[(size_t)gr * K + k0 + kq * 4]
                                : make_float4(0.f, 0.f, 0.f, 0.f);
            int rb = idx >> 5;                  // 0..15
            int cb = idx & 31;                  // 0..31
            b_reg[i] = *(const float4*)&B[(size_t)(k0 + rb) * N + col0 + cb * 4];
        }
    };
    auto sts_tile = [&](int buf) {
        #pragma unroll
        for (int i = 0; i < 2; i++) {
            int idx = tid + i * 256;
            int r  = idx >> 2;
            int kq = idx & 3;
            As[buf][kq * 4 + 0][r] = a_reg[i].x;
            As[buf][kq * 4 + 1][r] = a_reg[i].y;
            As[buf][kq * 4 + 2][r] = a_reg[i].z;
            As[buf][kq * 4 + 3][r] = a_reg[i].w;
            int rb = idx >> 5;
            int cb = idx & 31;
            *(float4*)&Bs[buf][rb][cb * 4] = b_reg[i];
        }
    };

    float acc[8][8] = {};

    ldg_tile(0);
    sts_tile(0);
    __syncthreads();

    int buf = 0;
    for (int k0 = 16; k0 <= K; k0 += 16) {
        bool more = (k0 < K);
        if (more) ldg_tile(k0);          // in flight during compute

        #pragma unroll
        for (int kk = 0; kk < 16; kk++) {
            float4 a0 = *(const float4*)&As[buf][kk][ty * 8];
            float4 a1 = *(const float4*)&As[buf][kk][ty * 8 + 4];
            float4 b0 = *(const float4*)&Bs[buf][kk][tx * 8];
            float4 b1 = *(const float4*)&Bs[buf][kk][tx * 8 + 4];
            float a[8] = {a0.x, a0.y, a0.z, a0.w, a1.x, a1.y, a1.z, a1.w};
            float b[8] = {b0.x, b0.y, b0.z, b0.w, b1.x, b1.y, b1.z, b1.w};
            #pragma unroll
            for (int i = 0; i < 8; i++)
                #pragma unroll
                for (int j = 0; j < 8; j++)
                    acc[i][j] += a[i] * b[j];
        }

        if (more) {
            sts_tile(buf ^ 1);
            __syncthreads();
            buf ^= 1;
        }
    }

    #pragma unroll
    for (int i = 0; i < 8; i++) {
        int r = row0 + ty * 8 + i;
        if (r < M) {
            float4 o0 = make_float4(acc[i][0], acc[i][1], acc[i][2], acc[i][3]);
            float4 o1 = make_float4(acc[i][4], acc[i][5], acc[i][6], acc[i][7]);
            *(float4*)&C[(size_t)r * N + col0 + tx * 8]     = o0;
            *(float4*)&C[(size_t)r * N + col0 + tx * 8 + 4] = o1;
        }
    }
}

// ---------------------------------------------------------------------------
// CSR gather: out[i,:] = dinv[i]^2*h[i,:] + sum_e w_e*h[src_e,:] + bias
// ---------------------------------------------------------------------------
template<int LAYER>
__global__ void k_gather(const float* __restrict__ bias,
                         float* __restrict__ outext) {
    constexpr int F = (LAYER == 0) ? FH : FO;
    constexpr int V = F / 128;
    const float* h   = (LAYER == 0) ? (const float*)g_h1 : (const float*)g_h2;
    float*       out = (LAYER == 0) ? g_agg1 : outext;

    int node = (blockIdx.x * blockDim.x + threadIdx.x) >> 5;
    int lane = threadIdx.x & 31;
    if (node >= NN) return;

    float4 acc[V];
    float wi = g_dinv[node];
    wi *= wi;
    const float4* hr = (const float4*)(h + (size_t)node * F);
    #pragma unroll
    for (int v = 0; v < V; v++) {
        float4 t = hr[lane + 32 * v];
        acc[v] = make_float4(wi * t.x, wi * t.y, wi * t.z, wi * t.w);
    }

    int beg = g_off[node];
    int end = beg + g_cnt[node];
    for (int e = beg; e < end; e++) {
        int   s = g_csr_src[e];
        float w = g_csr_w[e];
        const float4* sr = (const float4*)(h + (size_t)s * F);
        #pragma unroll
        for (int v = 0; v < V; v++) {
            float4 t = sr[lane + 32 * v];
            acc[v].x += w * t.x; acc[v].y += w * t.y;
            acc[v].z += w * t.z; acc[v].w += w * t.w;
        }
    }

    const float4* bv = (const float4*)bias;
    float4* ov = (float4*)(out + (size_t)node * F);
    #pragma unroll
    for (int v = 0; v < V; v++) {
        float4 b = bv[lane + 32 * v];
        float4 o = make_float4(acc[v].x + b.x, acc[v].y + b.y,
                               acc[v].z + b.z, acc[v].w + b.w);
        if (LAYER == 0) {
            o.x = fmaxf(o.x, 0.f); o.y = fmaxf(o.y, 0.f);
            o.z = fmaxf(o.z, 0.f); o.w = fmaxf(o.w, 0.f);
        }
        ov[lane + 32 * v] = o;
    }
}

// ---------------------------------------------------------------------------
// launch — inputs identified by element count (order-proof)
// ---------------------------------------------------------------------------
extern "C" void kernel_launch(void* const* d_in, const int* in_sizes, int n_in,
                              void* d_out, int out_size) {
    const float* x  = nullptr;
    const void*  ei = nullptr;
    const float* W1 = nullptr;
    const float* b1 = nullptr;
    const float* W2 = nullptr;
    const float* b2 = nullptr;

    for (int i = 0; i < n_in; i++) {
        switch (in_sizes[i]) {
            case NN * FIN:   x  = (const float*)d_in[i]; break;
            case 2 * NE:     ei = d_in[i];               break;
            case FIN * FH:   W1 = (const float*)d_in[i]; break;
            case FH:         b1 = (const float*)d_in[i]; break;
            case FH * FO:    W2 = (const float*)d_in[i]; break;
            case FO:         b2 = (const float*)d_in[i]; break;
            default: break;
        }
    }
    float* out = (float*)d_out;

    const int T = 256;

    k_detect   <<<1, 32>>>(ei);
    k_init     <<<(NN + T - 1) / T, T>>>();
    k_deg_count<<<(NE + T - 1) / T, T>>>(ei);
    k_dinv     <<<(NN + T - 1) / T, T>>>();
    k_scan     <<<1, 1024>>>();
    k_fill     <<<(NE + T - 1) / T, T>>>(ei);

    // layer 1: h1 = x @ W1 ; agg1 = relu(A_hat h1 + b1)
    {
        dim3 grid(FH / 128, (NN + 127) / 128);
        sgemm128<<<grid, 256>>>(x, W1, 0, NN, FH, FIN);
    }
    k_gather<0><<<((size_t)NN * 32 + T - 1) / T, T>>>(b1, nullptr);

    // layer 2: h2 = agg1 @ W2 ; out = A_hat h2 + b2
    {
        dim3 grid(FO / 128, (NN + 127) / 128);
        sgemm128<<<grid, 256>>>(nullptr, W2, 1, NN, FO, FH);
    }
    k_gather<1><<<((size_t)NN * 32 + T - 1) / T, T>>>(b2, out);
}

// round 10
// speedup vs baseline: 1.1128x; 1.1128x over previous
#include <cuda_runtime.h>
#include <cuda_bf16.h>
#include <stdint.h>

#define NN  50000
#define NE  800000
#define FIN 512
#define FH  256
#define FO  128

// ---- scratch: __device__ globals ----
__device__ int   g_is64;
__device__ __align__(16) float g_dinv[NN];
__device__ __align__(16) int   g_cnt [NN];
__device__ __align__(16) int   g_off [NN + 1];
__device__ __align__(16) int   g_fill[NN];
__device__ __align__(16) int   g_csr_src[NE];
__device__ __align__(16) float g_csr_w  [NE];
__device__ __align__(16) float g_h1  [(size_t)NN * FH];
__device__ __align__(16) float g_agg1[(size_t)NN * FH];
__device__ __align__(16) float g_h2  [(size_t)NN * FO];
// split buffers: A' up to [NN][3*FIN] bf16, B' up to [FH][3*FIN] bf16
__device__ __align__(16) __nv_bfloat16 g_Ap[(size_t)NN * 3 * FIN];
__device__ __align__(16) __nv_bfloat16 g_Bp[(size_t)FH * 3 * FIN];

// ---------------------------------------------------------------------------
// edge dtype detect (parallel) + decode
// ---------------------------------------------------------------------------
__global__ void k_detect(const void* __restrict__ ei) {
    const long long* p = (const long long*)ei;
    int lane = threadIdx.x;
    int bad = 0;
    #pragma unroll 4
    for (int i = lane; i < 2048; i += 32) {
        long long v = p[i];
        if (v < 0 || v >= NN) bad = 1;
    }
    unsigned m = __ballot_sync(0xffffffffu, bad);
    if (lane == 0) g_is64 = (m == 0);
}

__device__ __forceinline__ unsigned eidx(const void* __restrict__ ei, size_t idx) {
    if (g_is64) return (unsigned)((const long long*)ei)[idx];
    return (unsigned)((const int*)ei)[idx];
}

// ---------------------------------------------------------------------------
// degree / normalization / CSR build
// ---------------------------------------------------------------------------
__global__ void k_init() {
    int i = blockIdx.x * blockDim.x + threadIdx.x;
    if (i < NN) { g_cnt[i] = 0; g_fill[i] = 0; }
}

__global__ void k_deg_count(const void* __restrict__ ei) {
    int i = blockIdx.x * blockDim.x + threadIdx.x;
    if (i < NE) {
        unsigned d = eidx(ei, (size_t)NE + i);
        if (d < NN) atomicAdd(&g_cnt[d], 1);
    }
}

__global__ void k_dinv() {
    int i = blockIdx.x * blockDim.x + threadIdx.x;
    if (i < NN) g_dinv[i] = rsqrtf((float)(g_cnt[i] + 1));   // +1 self-loop
}

// single-block shuffle-based exclusive scan of g_cnt -> g_off
__global__ void k_scan() {
    __shared__ int wsum[32];
    __shared__ int carry;
    const int tid = threadIdx.x, lane = tid & 31, wid = tid >> 5;
    if (tid == 0) carry = 0;
    __syncthreads();

    for (int base = 0; base < NN; base += 1024) {
        int i = base + tid;
        int v = (i < NN) ? g_cnt[i] : 0;
        int s = v;
        #pragma unroll
        for (int o = 1; o < 32; o <<= 1) {
            int t = __shfl_up_sync(0xffffffffu, s, o);
            if (lane >= o) s += t;
        }
        if (lane == 31) wsum[wid] = s;
        __syncthreads();
        if (wid == 0) {
            int w = wsum[lane];
            #pragma unroll
            for (int o = 1; o < 32; o <<= 1) {
                int t = __shfl_up_sync(0xffffffffu, w, o);
                if (lane >= o) w += t;
            }
            wsum[lane] = w;       // inclusive warp-sum scan
        }
        __syncthreads();
        int woff  = (wid == 0) ? 0 : wsum[wid - 1];
        int total = wsum[31];
        if (i < NN) g_off[i] = carry + woff + s - v;   // exclusive
        __syncthreads();
        if (tid == 0) carry += total;
        __syncthreads();
    }
    if (threadIdx.x == 0) g_off[NN] = carry;
}

__global__ void k_fill(const void* __restrict__ ei) {
    int i = blockIdx.x * blockDim.x + threadIdx.x;
    if (i < NE) {
        unsigned s = eidx(ei, i);
        unsigned d = eidx(ei, (size_t)NE + i);
        if (s < NN && d < NN) {
            int pos = g_off[d] + atomicAdd(&g_fill[d], 1);
            if (pos < NE) {
                g_csr_src[pos] = (int)s;
                g_csr_w[pos]   = g_dinv[s] * g_dinv[d];
            }
        }
    }
}

// ---------------------------------------------------------------------------
// bf16 3-term split:  A'[m] = [hi(A) | lo(A) | hi(A)]   (row-major, [M][3K])
//                     B'[n] = [hi(B) | hi(B) | lo(B)]   (TRANSPOSED, [N][3K])
// so A' @ B'^T(k-contracted) = Ah*Bh + Al*Bh + Ah*Bl  (error ~2^-17)
// layer selects the source INSIDE the kernel (device symbols never cross host)
// ---------------------------------------------------------------------------
__global__ void k_split_a(const float* __restrict__ srcext, int layer,
                          int M, int K) {
    const float* src = (layer == 0) ? srcext : (const float*)g_agg1;
    size_t i = (size_t)blockIdx.x * blockDim.x + threadIdx.x;
    if (i >= (size_t)M * K) return;
    int m = (int)(i / K), k = (int)(i % K);
    float v = src[i];
    __nv_bfloat16 h = __float2bfloat16(v);
    __nv_bfloat16 l = __float2bfloat16(v - __bfloat162float(h));
    size_t base = (size_t)m * 3 * K;
    g_Ap[base + k]         = h;
    g_Ap[base + K + k]     = l;
    g_Ap[base + 2 * K + k] = h;
}

__global__ void k_split_b(const float* __restrict__ W, int K, int N) {
    int i = blockIdx.x * blockDim.x + threadIdx.x;
    if (i >= K * N) return;
    int k = i / N, n = i % N;
    float v = W[i];
    __nv_bfloat16 h = __float2bfloat16(v);
    __nv_bfloat16 l = __float2bfloat16(v - __bfloat162float(h));
    size_t base = (size_t)n * 3 * K;
    g_Bp[base + k]         = h;
    g_Bp[base + K + k]     = h;
    g_Bp[base + 2 * K + k] = l;
}

// ---------------------------------------------------------------------------
// bf16 mma GEMM: C[M,N] = A'[M,Kp] @ B'[N,Kp]^T  (both bf16, fp32 accum)
// BM=BN=128, BK=32, 256 thr = 8 warps (2m x 4n), warp tile 64x32,
// mma.sync.m16n8k16. smem row stride 20 words -> conflict-free LDS.
// layer 0 -> C = g_h1 ; layer 1 -> C = g_h2
// ---------------------------------------------------------------------------
#define SRS 20   // smem row stride in 32-bit words (40 bf16 = 80B)

__global__ void __launch_bounds__(256, 2)
mma_gemm(int layer, int M, int N, int Kp) {
    const __nv_bfloat16* A = g_Ap;
    const __nv_bfloat16* B = g_Bp;
    float* C = (layer == 0) ? g_h1 : g_h2;

    __shared__ uint32_t AsW[128 * SRS];
    __shared__ uint32_t BsW[128 * SRS];

    const int tid  = threadIdx.x;
    const int lane = tid & 31;
    const int wid  = tid >> 5;
    const int wm   = wid >> 2;          // 0..1  -> m offset wm*64
    const int wn   = wid & 3;           // 0..3  -> n offset wn*32
    const int row0 = blockIdx.y * 128;
    const int col0 = blockIdx.x * 128;

    const int lr = lane >> 2;           // 0..7
    const int lc = lane & 3;            // 0..3

    float acc[4][4][4];                 // [mi][ni][4]
    #pragma unroll
    for (int mi = 0; mi < 4; mi++)
        #pragma unroll
        for (int ni = 0; ni < 4; ni++)
            #pragma unroll
            for (int q = 0; q < 4; q++) acc[mi][ni][q] = 0.f;

    for (int k0 = 0; k0 < Kp; k0 += 32) {
        // ---- load A tile: 128 rows x 32 bf16, 2 x uint4 per thread ----
        #pragma unroll
        for (int i = 0; i < 2; i++) {
            int idx  = tid + i * 256;            // 0..511
            int r    = idx >> 2;                 // 0..127
            int ch   = idx & 3;                  // 0..3 (8 bf16 each)
            int gm   = row0 + r;
            uint4 v  = make_uint4(0u, 0u, 0u, 0u);
            if (gm < M)
                v = *(const uint4*)&A[(size_t)gm * Kp + k0 + ch * 8];
            *(uint4*)&AsW[r * SRS + ch * 4] = v;
        }
        // ---- load B tile: 128 n-rows x 32 bf16 (B' already [N][Kp]) ----
        #pragma unroll
        for (int i = 0; i < 2; i++) {
            int idx = tid + i * 256;
            int r   = idx >> 2;
            int ch  = idx & 3;
            int gn  = col0 + r;                  // N multiple of 128
            uint4 v = *(const uint4*)&B[(size_t)gn * Kp + k0 + ch * 8];
            *(uint4*)&BsW[r * SRS + ch * 4] = v;
        }
        __syncthreads();

        #pragma unroll
        for (int kk = 0; kk < 2; kk++) {        // two k16 steps
            const int kw = kk * 8;              // word offset (16 bf16)
            uint32_t afr[4][4];
            #pragma unroll
            for (int mi = 0; mi < 4; mi++) {
                int mrow = wm * 64 + mi * 16 + lr;
                int w0 = mrow * SRS + lc + kw;
                afr[mi][0] = AsW[w0];            // (r,   c)
                afr[mi][1] = AsW[w0 + 8 * SRS];  // (r+8, c)
                afr[mi][2] = AsW[w0 + 4];        // (r,   c+8)
                afr[mi][3] = AsW[w0 + 8 * SRS + 4];
            }
            uint32_t bfr[4][2];
            #pragma unroll
            for (int ni = 0; ni < 4; ni++) {
                int nrow = wn * 32 + ni * 8 + lr;
                int w0 = nrow * SRS + lc + kw;
                bfr[ni][0] = BsW[w0];
                bfr[ni][1] = BsW[w0 + 4];
            }
            #pragma unroll
            for (int mi = 0; mi < 4; mi++)
                #pragma unroll
                for (int ni = 0; ni < 4; ni++) {
                    asm volatile(
                        "mma.sync.aligned.m16n8k16.row.col.f32.bf16.bf16.f32 "
                        "{%0,%1,%2,%3}, {%4,%5,%6,%7}, {%8,%9}, {%0,%1,%2,%3};"
                        : "+f"(acc[mi][ni][0]), "+f"(acc[mi][ni][1]),
                          "+f"(acc[mi][ni][2]), "+f"(acc[mi][ni][3])
                        : "r"(afr[mi][0]), "r"(afr[mi][1]),
                          "r"(afr[mi][2]), "r"(afr[mi][3]),
                          "r"(bfr[ni][0]), "r"(bfr[ni][1]));
                }
        }
        __syncthreads();
    }

    // ---- epilogue: c0,c1 -> (r, 2c),(r,2c+1); c2,c3 -> (r+8, ...) ----
    #pragma unroll
    for (int mi = 0; mi < 4; mi++) {
        int r0 = row0 + wm * 64 + mi * 16 + lr;
        int r1 = r0 + 8;
        #pragma unroll
        for (int ni = 0; ni < 4; ni++) {
            int cb = col0 + wn * 32 + ni * 8 + lc * 2;
            if (r0 < M)
                *(float2*)&C[(size_t)r0 * N + cb] =
                    make_float2(acc[mi][ni][0], acc[mi][ni][1]);
            if (r1 < M)
                *(float2*)&C[(size_t)r1 * N + cb] =
                    make_float2(acc[mi][ni][2], acc[mi][ni][3]);
        }
    }
}

// ---------------------------------------------------------------------------
// CSR gather: out[i,:] = dinv[i]^2*h[i,:] + sum_e w_e*h[src_e,:] + bias
// ---------------------------------------------------------------------------
template<int LAYER>
__global__ void k_gather(const float* __restrict__ bias,
                         float* __restrict__ outext) {
    constexpr int F = (LAYER == 0) ? FH : FO;
    constexpr int V = F / 128;
    const float* h   = (LAYER == 0) ? (const float*)g_h1 : (const float*)g_h2;
    float*       out = (LAYER == 0) ? g_agg1 : outext;

    int node = (blockIdx.x * blockDim.x + threadIdx.x) >> 5;
    int lane = threadIdx.x & 31;
    if (node >= NN) return;

    float4 acc[V];
    float wi = g_dinv[node];
    wi *= wi;
    const float4* hr = (const float4*)(h + (size_t)node * F);
    #pragma unroll
    for (int v = 0; v < V; v++) {
        float4 t = hr[lane + 32 * v];
        acc[v] = make_float4(wi * t.x, wi * t.y, wi * t.z, wi * t.w);
    }

    int beg = g_off[node];
    int end = beg + g_cnt[node];
    for (int e = beg; e < end; e++) {
        int   s = g_csr_src[e];
        float w = g_csr_w[e];
        const float4* sr = (const float4*)(h + (size_t)s * F);
        #pragma unroll
        for (int v = 0; v < V; v++) {
            float4 t = sr[lane + 32 * v];
            acc[v].x += w * t.x; acc[v].y += w * t.y;
            acc[v].z += w * t.z; acc[v].w += w * t.w;
        }
    }

    const float4* bv = (const float4*)bias;
    float4* ov = (float4*)(out + (size_t)node * F);
    #pragma unroll
    for (int v = 0; v < V; v++) {
        float4 b = bv[lane + 32 * v];
        float4 o = make_float4(acc[v].x + b.x, acc[v].y + b.y,
                               acc[v].z + b.z, acc[v].w + b.w);
        if (LAYER == 0) {
            o.x = fmaxf(o.x, 0.f); o.y = fmaxf(o.y, 0.f);
            o.z = fmaxf(o.z, 0.f); o.w = fmaxf(o.w, 0.f);
        }
        ov[lane + 32 * v] = o;
    }
}

// ---------------------------------------------------------------------------
// launch — inputs identified by element count (order-proof)
// ---------------------------------------------------------------------------
extern "C" void kernel_launch(void* const* d_in, const int* in_sizes, int n_in,
                              void* d_out, int out_size) {
    const float* x  = nullptr;
    const void*  ei = nullptr;
    const float* W1 = nullptr;
    const float* b1 = nullptr;
    const float* W2 = nullptr;
    const float* b2 = nullptr;

    for (int i = 0; i < n_in; i++) {
        switch (in_sizes[i]) {
            case NN * FIN:   x  = (const float*)d_in[i]; break;
            case 2 * NE:     ei = d_in[i];               break;
            case FIN * FH:   W1 = (const float*)d_in[i]; break;
            case FH:         b1 = (const float*)d_in[i]; break;
            case FH * FO:    W2 = (const float*)d_in[i]; break;
            case FO:         b2 = (const float*)d_in[i]; break;
            default: break;
        }
    }
    float* out = (float*)d_out;

    const int T = 256;

    k_detect   <<<1, 32>>>(ei);
    k_init     <<<(NN + T - 1) / T, T>>>();
    k_deg_count<<<(NE + T - 1) / T, T>>>(ei);
    k_dinv     <<<(NN + T - 1) / T, T>>>();
    k_scan     <<<1, 1024>>>();
    k_fill     <<<(NE + T - 1) / T, T>>>(ei);

    // layer 1: h1 = x @ W1  (split-bf16 mma, K'=1536)
    k_split_a<<<(int)(((size_t)NN * FIN + T - 1) / T), T>>>(x, 0, NN, FIN);
    k_split_b<<<(FIN * FH + T - 1) / T, T>>>(W1, FIN, FH);
    {
        dim3 grid(FH / 128, (NN + 127) / 128);
        mma_gemm<<<grid, 256>>>(0, NN, FH, 3 * FIN);
    }
    k_gather<0><<<((size_t)NN * 32 + T - 1) / T, T>>>(b1, nullptr);

    // layer 2: h2 = agg1 @ W2  (split-bf16 mma, K'=768)
    k_split_a<<<(int)(((size_t)NN * FH + T - 1) / T), T>>>(nullptr, 1, NN, FH);
    k_split_b<<<(FH * FO + T - 1) / T, T>>>(W2, FH, FO);
    {
        dim3 grid(FO / 128, (NN + 127) / 128);
        mma_gemm<<<grid, 256>>>(1, NN, FO, 3 * FH);
    }
    k_gather<1><<<((size_t)NN * 32 + T - 1) / T, T>>>(b2, out);
}

// round 11
// speedup vs baseline: 1.8726x; 1.6827x over previous
#include <cuda_runtime.h>
#include <cuda_fp16.h>
#include <stdint.h>

#define NN  50000
#define NE  800000
#define FIN 512
#define FH  256
#define FO  128

// ---- scratch: __device__ globals ----
__device__ int   g_is64;
__device__ __align__(16) float g_dinv[NN];
__device__ __align__(16) int   g_cnt [NN];
__device__ __align__(16) int   g_off [NN + 1];
__device__ __align__(16) int   g_fill[NN];
__device__ __align__(16) int   g_csr_src[NE];
__device__ __align__(16) float g_csr_w  [NE];
__device__ __align__(16) float g_h1  [(size_t)NN * FH];
__device__ __align__(16) float g_agg1[(size_t)NN * FH];
__device__ __align__(16) float g_h2  [(size_t)NN * FO];
// B in fp16, transposed [N][K] (hi part only; A carries exact hi+lo)
__device__ __align__(16) __half g_Bh[(size_t)FH * FIN];

// ---------------------------------------------------------------------------
// edge dtype detect (parallel) + decode
// ---------------------------------------------------------------------------
__global__ void k_detect(const void* __restrict__ ei) {
    const long long* p = (const long long*)ei;
    int lane = threadIdx.x;
    int bad = 0;
    #pragma unroll 4
    for (int i = lane; i < 2048; i += 32) {
        long long v = p[i];
        if (v < 0 || v >= NN) bad = 1;
    }
    unsigned m = __ballot_sync(0xffffffffu, bad);
    if (lane == 0) g_is64 = (m == 0);
}

__device__ __forceinline__ unsigned eidx(const void* __restrict__ ei, size_t idx) {
    if (g_is64) return (unsigned)((const long long*)ei)[idx];
    return (unsigned)((const int*)ei)[idx];
}

// ---------------------------------------------------------------------------
// degree / normalization / CSR build
// ---------------------------------------------------------------------------
__global__ void k_init() {
    int i = blockIdx.x * blockDim.x + threadIdx.x;
    if (i < NN) { g_cnt[i] = 0; g_fill[i] = 0; }
}

__global__ void k_deg_count(const void* __restrict__ ei) {
    int i = blockIdx.x * blockDim.x + threadIdx.x;
    if (i < NE) {
        unsigned d = eidx(ei, (size_t)NE + i);
        if (d < NN) atomicAdd(&g_cnt[d], 1);
    }
}

__global__ void k_dinv() {
    int i = blockIdx.x * blockDim.x + threadIdx.x;
    if (i < NN) g_dinv[i] = rsqrtf((float)(g_cnt[i] + 1));   // +1 self-loop
}

// single-block shuffle-based exclusive scan of g_cnt -> g_off
__global__ void k_scan() {
    __shared__ int wsum[32];
    __shared__ int carry;
    const int tid = threadIdx.x, lane = tid & 31, wid = tid >> 5;
    if (tid == 0) carry = 0;
    __syncthreads();

    for (int base = 0; base < NN; base += 1024) {
        int i = base + tid;
        int v = (i < NN) ? g_cnt[i] : 0;
        int s = v;
        #pragma unroll
        for (int o = 1; o < 32; o <<= 1) {
            int t = __shfl_up_sync(0xffffffffu, s, o);
            if (lane >= o) s += t;
        }
        if (lane == 31) wsum[wid] = s;
        __syncthreads();
        if (wid == 0) {
            int w = wsum[lane];
            #pragma unroll
            for (int o = 1; o < 32; o <<= 1) {
                int t = __shfl_up_sync(0xffffffffu, w, o);
                if (lane >= o) w += t;
            }
            wsum[lane] = w;
        }
        __syncthreads();
        int woff  = (wid == 0) ? 0 : wsum[wid - 1];
        int total = wsum[31];
        if (i < NN) g_off[i] = carry + woff + s - v;
        __syncthreads();
        if (tid == 0) carry += total;
        __syncthreads();
    }
    if (threadIdx.x == 0) g_off[NN] = carry;
}

__global__ void k_fill(const void* __restrict__ ei) {
    int i = blockIdx.x * blockDim.x + threadIdx.x;
    if (i < NE) {
        unsigned s = eidx(ei, i);
        unsigned d = eidx(ei, (size_t)NE + i);
        if (s < NN && d < NN) {
            int pos = g_off[d] + atomicAdd(&g_fill[d], 1);
            if (pos < NE) {
                g_csr_src[pos] = (int)s;
                g_csr_w[pos]   = g_dinv[s] * g_dinv[d];
            }
        }
    }
}

// ---------------------------------------------------------------------------
// B convert: W [K][N] fp32 -> g_Bh [N][K] fp16 (transposed, hi only)
// ---------------------------------------------------------------------------
__global__ void k_conv_b(const float* __restrict__ W, int K, int N) {
    int i = blockIdx.x * blockDim.x + threadIdx.x;
    if (i >= K * N) return;
    int k = i / N, n = i % N;
    g_Bh[(size_t)n * K + k] = __float2half(W[i]);
}

// ---------------------------------------------------------------------------
// fp16 split-mma GEMM: C[M,N] = A[M,K](fp32) @ B[N,K](fp16)^T, fp32 accum
// A split to (hi,lo) fp16 in-kernel: C = Ah*B + Al*B  (A exact, B fp16-rounded)
// BM=BN=128, BK=32, 256 thr = 8 warps (2m x 4n), warp tile 64x32.
// ldmatrix x4 fragment loads; smem stride 40 halfs (80B: 16B-aligned rows,
// conflict-free: row word-offsets 20i mod 32 distinct over 8 rows).
// layer 0: A = xext, C = g_h1 ;  layer 1: A = g_agg1, C = g_h2
// ---------------------------------------------------------------------------
#define SRH 40   // smem row stride in halfs

#define LDSM_X4(r0, r1, r2, r3, addr)                                        \
    asm volatile("ldmatrix.sync.aligned.m8n8.x4.shared.b16 {%0,%1,%2,%3}, [%4];" \
                 : "=r"(r0), "=r"(r1), "=r"(r2), "=r"(r3) : "r"(addr))

__global__ void __launch_bounds__(256)
mma_gemm(const float* __restrict__ Aext, int layer, int M, int N, int K) {
    const float* A = (layer == 0) ? Aext : (const float*)g_agg1;
    float*       C = (layer == 0) ? g_h1 : g_h2;
    const __half* B = g_Bh;

    __shared__ __align__(16) __half As_h[128 * SRH];
    __shared__ __align__(16) __half As_l[128 * SRH];
    __shared__ __align__(16) __half Bs  [128 * SRH];

    const int tid  = threadIdx.x;
    const int lane = tid & 31;
    const int wid  = tid >> 5;
    const int wm   = wid >> 2;            // 0..1 -> m offset wm*64
    const int wn   = wid & 3;             // 0..3 -> n offset wn*32
    const int row0 = blockIdx.y * 128;
    const int col0 = blockIdx.x * 128;

    const uint32_t sAh = (uint32_t)__cvta_generic_to_shared(As_h);
    const uint32_t sAl = (uint32_t)__cvta_generic_to_shared(As_l);
    const uint32_t sB  = (uint32_t)__cvta_generic_to_shared(Bs);

    // per-thread tile-load coords: row r, 16-wide column half
    const int ldr = tid >> 1;              // 0..127
    const int ldc = (tid & 1) * 16;        // 0 or 16

    float acc[4][4][4];
    #pragma unroll
    for (int mi = 0; mi < 4; mi++)
        #pragma unroll
        for (int ni = 0; ni < 4; ni++)
            #pragma unroll
            for (int q = 0; q < 4; q++) acc[mi][ni][q] = 0.f;

    // ldmatrix per-lane addresses (byte offsets computed once)
    const int a_row = (lane & 15);
    const int a_colh = (lane >> 4) * 8;
    const int b_row = (lane >> 4) * 8 + (lane & 7);
    const int b_colh = ((lane >> 3) & 1) * 8;

    for (int k0 = 0; k0 < K; k0 += 32) {
        // ---- A tile: 128 x 32 fp32 -> split into As_h / As_l ----
        {
            int gm = row0 + ldr;
            const float* ap = A + (size_t)gm * K + k0 + ldc;
            __half2* hh = (__half2*)&As_h[ldr * SRH + ldc];
            __half2* hl = (__half2*)&As_l[ldr * SRH + ldc];
            #pragma unroll
            for (int j = 0; j < 4; j++) {
                float4 v = (gm < M) ? *(const float4*)(ap + 4 * j)
                                    : make_float4(0.f, 0.f, 0.f, 0.f);
                __half hx = __float2half(v.x), hy = __float2half(v.y);
                __half hz = __float2half(v.z), hw = __float2half(v.w);
                hh[2 * j]     = __halves2half2(hx, hy);
                hh[2 * j + 1] = __halves2half2(hz, hw);
                hl[2 * j]     = __halves2half2(__float2half(v.x - __half2float(hx)),
                                               __float2half(v.y - __half2float(hy)));
                hl[2 * j + 1] = __halves2half2(__float2half(v.z - __half2float(hz)),
                                               __float2half(v.w - __half2float(hw)));
            }
        }
        // ---- B tile: 128 x 32 fp16 (already [N][K]) ----
        {
            int gn = col0 + ldr;                // N multiple of 128
            const __half* bp = B + (size_t)gn * K + k0 + ldc;
            #pragma unroll
            for (int j = 0; j < 2; j++) {
                uint4 v = *(const uint4*)(bp + 8 * j);
                *(uint4*)&Bs[ldr * SRH + ldc + 8 * j] = v;
            }
        }
        __syncthreads();

        #pragma unroll
        for (int kk = 0; kk < 2; kk++) {
            const int kh = kk * 16;
            // B fragments: 2 x ldmatrix.x4 covering ni 0..3
            uint32_t bfr[4][2];
            #pragma unroll
            for (int nip = 0; nip < 2; nip++) {
                uint32_t addr = sB +
                    (uint32_t)(((wn * 32 + nip * 16 + b_row) * SRH + kh + b_colh) * 2);
                LDSM_X4(bfr[2 * nip][0], bfr[2 * nip][1],
                        bfr[2 * nip + 1][0], bfr[2 * nip + 1][1], addr);
            }
            // two A parts: hi then lo (fragments reuse registers)
            #pragma unroll
            for (int part = 0; part < 2; part++) {
                const uint32_t sA = part ? sAl : sAh;
                uint32_t afr[4][4];
                #pragma unroll
                for (int mi = 0; mi < 4; mi++) {
                    uint32_t addr = sA +
                        (uint32_t)(((wm * 64 + mi * 16 + a_row) * SRH + kh + a_colh) * 2);
                    LDSM_X4(afr[mi][0], afr[mi][1], afr[mi][2], afr[mi][3], addr);
                }
                #pragma unroll
                for (int mi = 0; mi < 4; mi++)
                    #pragma unroll
                    for (int ni = 0; ni < 4; ni++) {
                        asm volatile(
                            "mma.sync.aligned.m16n8k16.row.col.f32.f16.f16.f32 "
                            "{%0,%1,%2,%3}, {%4,%5,%6,%7}, {%8,%9}, {%0,%1,%2,%3};"
                            : "+f"(acc[mi][ni][0]), "+f"(acc[mi][ni][1]),
                              "+f"(acc[mi][ni][2]), "+f"(acc[mi][ni][3])
                            : "r"(afr[mi][0]), "r"(afr[mi][1]),
                              "r"(afr[mi][2]), "r"(afr[mi][3]),
                              "r"(bfr[ni][0]), "r"(bfr[ni][1]));
                    }
            }
        }
        __syncthreads();
    }

    // epilogue: c0,c1 -> (r, 2c),(r,2c+1); c2,c3 -> (r+8, ...)
    const int lr = lane >> 2, lc = lane & 3;
    #pragma unroll
    for (int mi = 0; mi < 4; mi++) {
        int r0 = row0 + wm * 64 + mi * 16 + lr;
        int r1 = r0 + 8;
        #pragma unroll
        for (int ni = 0; ni < 4; ni++) {
            int cb = col0 + wn * 32 + ni * 8 + lc * 2;
            if (r0 < M)
                *(float2*)&C[(size_t)r0 * N + cb] =
                    make_float2(acc[mi][ni][0], acc[mi][ni][1]);
            if (r1 < M)
                *(float2*)&C[(size_t)r1 * N + cb] =
                    make_float2(acc[mi][ni][2], acc[mi][ni][3]);
        }
    }
}

// ---------------------------------------------------------------------------
// CSR gather: out[i,:] = dinv[i]^2*h[i,:] + sum_e w_e*h[src_e,:] + bias
// ---------------------------------------------------------------------------
template<int LAYER>
__global__ void k_gather(const float* __restrict__ bias,
                         float* __restrict__ outext) {
    constexpr int F = (LAYER == 0) ? FH : FO;
    constexpr int V = F / 128;
    const float* h   = (LAYER == 0) ? (const float*)g_h1 : (const float*)g_h2;
    float*       out = (LAYER == 0) ? g_agg1 : outext;

    int node = (blockIdx.x * blockDim.x + threadIdx.x) >> 5;
    int lane = threadIdx.x & 31;
    if (node >= NN) return;

    float4 acc[V];
    float wi = g_dinv[node];
    wi *= wi;
    const float4* hr = (const float4*)(h + (size_t)node * F);
    #pragma unroll
    for (int v = 0; v < V; v++) {
        float4 t = hr[lane + 32 * v];
        acc[v] = make_float4(wi * t.x, wi * t.y, wi * t.z, wi * t.w);
    }

    int beg = g_off[node];
    int end = beg + g_cnt[node];
    for (int e = beg; e < end; e++) {
        int   s = g_csr_src[e];
        float w = g_csr_w[e];
        const float4* sr = (const float4*)(h + (size_t)s * F);
        #pragma unroll
        for (int v = 0; v < V; v++) {
            float4 t = sr[lane + 32 * v];
            acc[v].x += w * t.x; acc[v].y += w * t.y;
            acc[v].z += w * t.z; acc[v].w += w * t.w;
        }
    }

    const float4* bv = (const float4*)bias;
    float4* ov = (float4*)(out + (size_t)node * F);
    #pragma unroll
    for (int v = 0; v < V; v++) {
        float4 b = bv[lane + 32 * v];
        float4 o = make_float4(acc[v].x + b.x, acc[v].y + b.y,
                               acc[v].z + b.z, acc[v].w + b.w);
        if (LAYER == 0) {
            o.x = fmaxf(o.x, 0.f); o.y = fmaxf(o.y, 0.f);
            o.z = fmaxf(o.z, 0.f); o.w = fmaxf(o.w, 0.f);
        }
        ov[lane + 32 * v] = o;
    }
}

// ---------------------------------------------------------------------------
// launch — inputs identified by element count (order-proof)
// ---------------------------------------------------------------------------
extern "C" void kernel_launch(void* const* d_in, const int* in_sizes, int n_in,
                              void* d_out, int out_size) {
    const float* x  = nullptr;
    const void*  ei = nullptr;
    const float* W1 = nullptr;
    const float* b1 = nullptr;
    const float* W2 = nullptr;
    const float* b2 = nullptr;

    for (int i = 0; i < n_in; i++) {
        switch (in_sizes[i]) {
            case NN * FIN:   x  = (const float*)d_in[i]; break;
            case 2 * NE:     ei = d_in[i];               break;
            case FIN * FH:   W1 = (const float*)d_in[i]; break;
            case FH:         b1 = (const float*)d_in[i]; break;
            case FH * FO:    W2 = (const float*)d_in[i]; break;
            case FO:         b2 = (const float*)d_in[i]; break;
            default: break;
        }
    }
    float* out = (float*)d_out;

    const int T = 256;

    k_detect   <<<1, 32>>>(ei);
    k_init     <<<(NN + T - 1) / T, T>>>();
    k_deg_count<<<(NE + T - 1) / T, T>>>(ei);
    k_dinv     <<<(NN + T - 1) / T, T>>>();
    k_scan     <<<1, 1024>>>();
    k_fill     <<<(NE + T - 1) / T, T>>>(ei);

    // layer 1: h1 = x @ W1
    k_conv_b<<<(FIN * FH + T - 1) / T, T>>>(W1, FIN, FH);
    {
        dim3 grid(FH / 128, (NN + 127) / 128);
        mma_gemm<<<grid, 256>>>(x, 0, NN, FH, FIN);
    }
    k_gather<0><<<((size_t)NN * 32 + T - 1) / T, T>>>(b1, nullptr);

    // layer 2: h2 = agg1 @ W2
    k_conv_b<<<(FH * FO + T - 1) / T, T>>>(W2, FH, FO);
    {
        dim3 grid(FO / 128, (NN + 127) / 128);
        mma_gemm<<<grid, 256>>>(nullptr, 1, NN, FO, FH);
    }
    k_gather<1><<<((size_t)NN * 32 + T - 1) / T, T>>>(b2, out);
}

// round 12
// speedup vs baseline: 2.0042x; 1.0703x over previous
#include <cuda_runtime.h>
#include <cuda_fp16.h>
#include <stdint.h>

#define NN  50000
#define NE  800000
#define FIN 512
#define FH  256
#define FO  128

// ---- scratch: __device__ globals ----
__device__ int   g_is64;
__device__ __align__(16) float g_dinv[NN];
__device__ __align__(16) int   g_cnt [NN];
__device__ __align__(16) int   g_off [NN + 1];
__device__ __align__(16) int   g_fill[NN];
__device__ __align__(16) int   g_blk [256];
__device__ __align__(16) int   g_csr_src[NE];
__device__ __align__(16) float g_csr_w  [NE];
__device__ __align__(16) float g_h1  [(size_t)NN * FH];
__device__ __align__(16) float g_agg1[(size_t)NN * FH];
__device__ __align__(16) float g_h2  [(size_t)NN * FO];
// B in fp16, transposed [N][K]
__device__ __align__(16) __half g_Bh[(size_t)FH * FIN];

// ---------------------------------------------------------------------------
// edge dtype detect (parallel) + decode
// ---------------------------------------------------------------------------
__global__ void k_detect(const void* __restrict__ ei) {
    const long long* p = (const long long*)ei;
    int lane = threadIdx.x;
    int bad = 0;
    #pragma unroll 4
    for (int i = lane; i < 2048; i += 32) {
        long long v = p[i];
        if (v < 0 || v >= NN) bad = 1;
    }
    unsigned m = __ballot_sync(0xffffffffu, bad);
    if (lane == 0) g_is64 = (m == 0);
}

__device__ __forceinline__ unsigned eidx(const void* __restrict__ ei, size_t idx) {
    if (g_is64) return (unsigned)((const long long*)ei)[idx];
    return (unsigned)((const int*)ei)[idx];
}

// ---------------------------------------------------------------------------
// degree / normalization / CSR build
// ---------------------------------------------------------------------------
__global__ void k_init() {
    int i = blockIdx.x * blockDim.x + threadIdx.x;
    if (i < NN) { g_cnt[i] = 0; g_fill[i] = 0; }
}

__global__ void k_deg_count(const void* __restrict__ ei) {
    int i = blockIdx.x * blockDim.x + threadIdx.x;
    if (i < NE) {
        unsigned d = eidx(ei, (size_t)NE + i);
        if (d < NN) atomicAdd(&g_cnt[d], 1);
    }
}

__global__ void k_dinv() {
    int i = blockIdx.x * blockDim.x + threadIdx.x;
    if (i < NN) g_dinv[i] = rsqrtf((float)(g_cnt[i] + 1));   // +1 self-loop
}

// ---- 3-phase parallel exclusive scan of g_cnt -> g_off ----
// phase 1: per-block (256) exclusive scan; block total -> g_blk
__global__ void k_scan1() {
    __shared__ int wsum[8];
    int i = blockIdx.x * 256 + threadIdx.x;
    int lane = threadIdx.x & 31, wid = threadIdx.x >> 5;
    int v = (i < NN) ? g_cnt[i] : 0;
    int s = v;
    #pragma unroll
    for (int o = 1; o < 32; o <<= 1) {
        int t = __shfl_up_sync(0xffffffffu, s, o);
        if (lane >= o) s += t;
    }
    if (lane == 31) wsum[wid] = s;
    __syncthreads();
    if (wid == 0 && lane < 8) {
        int w = wsum[lane];
        #pragma unroll
        for (int o = 1; o < 8; o <<= 1) {
            int t = __shfl_up_sync(0xffu, w, o);
            if (lane >= o) w += t;
        }
        wsum[lane] = w;
    }
    __syncthreads();
    int woff = (wid == 0) ? 0 : wsum[wid - 1];
    if (i < NN) g_off[i] = woff + s - v;
    if (threadIdx.x == 255) g_blk[blockIdx.x] = woff + s;
}

// phase 2: single block scans 196 block totals (exclusive, in place)
__global__ void k_scan2(int nblk) {
    __shared__ int wsum[8];
    int lane = threadIdx.x & 31, wid = threadIdx.x >> 5;
    int v = (threadIdx.x < nblk) ? g_blk[threadIdx.x] : 0;
    int s = v;
    #pragma unroll
    for (int o = 1; o < 32; o <<= 1) {
        int t = __shfl_up_sync(0xffffffffu, s, o);
        if (lane >= o) s += t;
    }
    if (lane == 31) wsum[wid] = s;
    __syncthreads();
    if (wid == 0 && lane < 8) {
        int w = wsum[lane];
        #pragma unroll
        for (int o = 1; o < 8; o <<= 1) {
            int t = __shfl_up_sync(0xffu, w, o);
            if (lane >= o) w += t;
        }
        wsum[lane] = w;
    }
    __syncthreads();
    int woff = (wid == 0) ? 0 : wsum[wid - 1];
    if (threadIdx.x < nblk) g_blk[threadIdx.x] = woff + s - v;
    if (threadIdx.x == 255) g_off[NN] = woff + s;
}

// phase 3: add block offsets
__global__ void k_scan3() {
    int i = blockIdx.x * 256 + threadIdx.x;
    if (i < NN) g_off[i] += g_blk[i >> 8];
}

__global__ void k_fill(const void* __restrict__ ei) {
    int i = blockIdx.x * blockDim.x + threadIdx.x;
    if (i < NE) {
        unsigned s = eidx(ei, i);
        unsigned d = eidx(ei, (size_t)NE + i);
        if (s < NN && d < NN) {
            int pos = g_off[d] + atomicAdd(&g_fill[d], 1);
            if (pos < NE) {
                g_csr_src[pos] = (int)s;
                g_csr_w[pos]   = g_dinv[s] * g_dinv[d];
            }
        }
    }
}

// ---------------------------------------------------------------------------
// B convert: W [K][N] fp32 -> g_Bh [N][K] fp16 (transposed, hi only)
// ---------------------------------------------------------------------------
__global__ void k_conv_b(const float* __restrict__ W, int K, int N) {
    int i = blockIdx.x * blockDim.x + threadIdx.x;
    if (i >= K * N) return;
    int k = i / N, n = i % N;
    g_Bh[(size_t)n * K + k] = __float2half(W[i]);
}

// ---------------------------------------------------------------------------
// fp16 split-mma GEMM with cp.async double buffering.
// C[M,N] = A[M,K](fp32) @ B[N,K](fp16)^T, fp32 accum; A split hi+lo in-kernel.
// BM=BN=128, BK=32, 256 thr = 8 warps (2m x 4n).
// Dynamic smem (96KB): stageA fp32 x2, Bs fp16 x2, Ah/Al fp16 x2.
// ---------------------------------------------------------------------------
#define SRH 40          // Ah/Al/Bs row stride in halfs (80B)
#define SRF 36          // stageA row stride in floats (144B)
#define SZ_STAGEA (128 * SRF * 4)      // 18432 B per buffer
#define SZ_HTILE  (128 * SRH * 2)      // 10240 B per buffer
#define OFF_STAGEA 0
#define OFF_BS  (2 * SZ_STAGEA)                   // 36864
#define OFF_AH  (OFF_BS + 2 * SZ_HTILE)           // 57344
#define OFF_AL  (OFF_AH + 2 * SZ_HTILE)           // 77824
#define SMEM_TOTAL (OFF_AL + 2 * SZ_HTILE)        // 98304

#define LDSM_X4(r0, r1, r2, r3, addr)                                        \
    asm volatile("ldmatrix.sync.aligned.m8n8.x4.shared.b16 {%0,%1,%2,%3}, [%4];" \
                 : "=r"(r0), "=r"(r1), "=r"(r2), "=r"(r3) : "r"(addr))

__device__ __forceinline__ void cp16(uint32_t dst, const void* src, int srcsz) {
    asm volatile("cp.async.cg.shared.global [%0], [%1], 16, %2;"
                 :: "r"(dst), "l"(src), "r"(srcsz));
}

__global__ void __launch_bounds__(256)
mma_gemm(const float* __restrict__ Aext, int layer, int M, int N, int K) {
    const float*  A = (layer == 0) ? Aext : (const float*)g_agg1;
    float*        C = (layer == 0) ? g_h1 : g_h2;
    const __half* B = g_Bh;

    extern __shared__ __align__(16) char dyn[];
    const uint32_t sbase = (uint32_t)__cvta_generic_to_shared(dyn);

    const int tid  = threadIdx.x;
    const int lane = tid & 31;
    const int wid  = tid >> 5;
    const int wm   = wid >> 2;
    const int wn   = wid & 3;
    const int row0 = blockIdx.y * 128;
    const int col0 = blockIdx.x * 128;

    const int ldr = tid >> 1;            // 0..127
    const int ldc = (tid & 1) * 16;      // 0 or 16

    const int gm = row0 + ldr;
    const int gn = col0 + ldr;
    const int a_ok = (gm < M) ? 16 : 0;
    const float* a_base = A + (size_t)gm * K + ldc;
    const __half* b_base = B + (size_t)gn * K + ldc;
    const uint32_t da = sbase + OFF_STAGEA + (uint32_t)((ldr * SRF + ldc) * 4);
    const uint32_t db = sbase + OFF_BS     + (uint32_t)((ldr * SRH + ldc) * 2);

    float acc[4][4][4];
    #pragma unroll
    for (int mi = 0; mi < 4; mi++)
        #pragma unroll
        for (int ni = 0; ni < 4; ni++)
            #pragma unroll
            for (int q = 0; q < 4; q++) acc[mi][ni][q] = 0.f;

    const int a_row  = (lane & 15);
    const int a_colh = (lane >> 4) * 8;
    const int b_row  = (lane >> 4) * 8 + (lane & 7);
    const int b_colh = ((lane >> 3) & 1) * 8;

    const int NC = K >> 5;               // 32-k chunks

    // prologue: issue chunk 0 into buffer 0
    {
        #pragma unroll
        for (int j = 0; j < 4; j++) cp16(da + j * 16, a_base + j * 4, a_ok);
        #pragma unroll
        for (int j = 0; j < 2; j++) cp16(db + j * 16, b_base + j * 8, 16);
        asm volatile("cp.async.commit_group;");
    }

    int buf = 0;
    for (int c = 0; c < NC; c++) {
        asm volatile("cp.async.wait_group 0;");
        __syncthreads();                 // chunk c staged; all warps done mma(c-1)

        if (c + 1 < NC) {                // issue chunk c+1 into buf^1
            int k0 = (c + 1) * 32;
            uint32_t da2 = da + (buf ^ 1) * SZ_STAGEA;
            uint32_t db2 = db + (buf ^ 1) * SZ_HTILE;
            #pragma unroll
            for (int j = 0; j < 4; j++) cp16(da2 + j * 16, a_base + k0 + j * 4, a_ok);
            #pragma unroll
            for (int j = 0; j < 2; j++) cp16(db2 + j * 16, b_base + k0 + j * 8, 16);
            asm volatile("cp.async.commit_group;");
        }

        // convert stageA[buf] (fp32) -> Ah[buf], Al[buf] (fp16 hi/lo)
        {
            const float4* src = (const float4*)(dyn + OFF_STAGEA + buf * SZ_STAGEA
                                                + (ldr * SRF + ldc) * 4);
            __half2* hh = (__half2*)(dyn + OFF_AH + buf * SZ_HTILE
                                     + (ldr * SRH + ldc) * 2);
            __half2* hl = (__half2*)(dyn + OFF_AL + buf * SZ_HTILE
                                     + (ldr * SRH + ldc) * 2);
            #pragma unroll
            for (int j = 0; j < 4; j++) {
                float4 v = src[j];
                __half hx = __float2half(v.x), hy = __float2half(v.y);
                __half hz = __float2half(v.z), hw = __float2half(v.w);
                hh[2 * j]     = __halves2half2(hx, hy);
                hh[2 * j + 1] = __halves2half2(hz, hw);
                hl[2 * j]     = __halves2half2(__float2half(v.x - __half2float(hx)),
                                               __float2half(v.y - __half2float(hy)));
                hl[2 * j + 1] = __halves2half2(__float2half(v.z - __half2float(hz)),
                                               __float2half(v.w - __half2float(hw)));
            }
        }
        __syncthreads();                 // Ah/Al[buf] visible

        const uint32_t sAh = sbase + OFF_AH + buf * SZ_HTILE;
        const uint32_t sAl = sbase + OFF_AL + buf * SZ_HTILE;
        const uint32_t sB  = sbase + OFF_BS + buf * SZ_HTILE;

        #pragma unroll
        for (int kk = 0; kk < 2; kk++) {
            const int kh = kk * 16;
            uint32_t bfr[4][2];
            #pragma unroll
            for (int nip = 0; nip < 2; nip++) {
                uint32_t addr = sB +
                    (uint32_t)(((wn * 32 + nip * 16 + b_row) * SRH + kh + b_colh) * 2);
                LDSM_X4(bfr[2 * nip][0], bfr[2 * nip][1],
                        bfr[2 * nip + 1][0], bfr[2 * nip + 1][1], addr);
            }
            #pragma unroll
            for (int part = 0; part < 2; part++) {
                const uint32_t sA = part ? sAl : sAh;
                uint32_t afr[4][4];
                #pragma unroll
                for (int mi = 0; mi < 4; mi++) {
                    uint32_t addr = sA +
                        (uint32_t)(((wm * 64 + mi * 16 + a_row) * SRH + kh + a_colh) * 2);
                    LDSM_X4(afr[mi][0], afr[mi][1], afr[mi][2], afr[mi][3], addr);
                }
                #pragma unroll
                for (int mi = 0; mi < 4; mi++)
                    #pragma unroll
                    for (int ni = 0; ni < 4; ni++) {
                        asm volatile(
                            "mma.sync.aligned.m16n8k16.row.col.f32.f16.f16.f32 "
                            "{%0,%1,%2,%3}, {%4,%5,%6,%7}, {%8,%9}, {%0,%1,%2,%3};"
                            : "+f"(acc[mi][ni][0]), "+f"(acc[mi][ni][1]),
                              "+f"(acc[mi][ni][2]), "+f"(acc[mi][ni][3])
                            : "r"(afr[mi][0]), "r"(afr[mi][1]),
                              "r"(afr[mi][2]), "r"(afr[mi][3]),
                              "r"(bfr[ni][0]), "r"(bfr[ni][1]));
                    }
            }
        }
        buf ^= 1;
    }

    const int lr = lane >> 2, lc = lane & 3;
    #pragma unroll
    for (int mi = 0; mi < 4; mi++) {
        int r0 = row0 + wm * 64 + mi * 16 + lr;
        int r1 = r0 + 8;
        #pragma unroll
        for (int ni = 0; ni < 4; ni++) {
            int cb = col0 + wn * 32 + ni * 8 + lc * 2;
            if (r0 < M)
                *(float2*)&C[(size_t)r0 * N + cb] =
                    make_float2(acc[mi][ni][0], acc[mi][ni][1]);
            if (r1 < M)
                *(float2*)&C[(size_t)r1 * N + cb] =
                    make_float2(acc[mi][ni][2], acc[mi][ni][3]);
        }
    }
}

// ---------------------------------------------------------------------------
// CSR gather: out[i,:] = dinv[i]^2*h[i,:] + sum_e w_e*h[src_e,:] + bias
// ---------------------------------------------------------------------------
template<int LAYER>
__global__ void k_gather(const float* __restrict__ bias,
                         float* __restrict__ outext) {
    constexpr int F = (LAYER == 0) ? FH : FO;
    constexpr int V = F / 128;
    const float* h   = (LAYER == 0) ? (const float*)g_h1 : (const float*)g_h2;
    float*       out = (LAYER == 0) ? g_agg1 : outext;

    int node = (blockIdx.x * blockDim.x + threadIdx.x) >> 5;
    int lane = threadIdx.x & 31;
    if (node >= NN) return;

    float4 acc[V];
    float wi = g_dinv[node];
    wi *= wi;
    const float4* hr = (const float4*)(h + (size_t)node * F);
    #pragma unroll
    for (int v = 0; v < V; v++) {
        float4 t = hr[lane + 32 * v];
        acc[v] = make_float4(wi * t.x, wi * t.y, wi * t.z, wi * t.w);
    }

    int beg = g_off[node];
    int end = beg + g_cnt[node];
    for (int e = beg; e < end; e++) {
        int   s = g_csr_src[e];
        float w = g_csr_w[e];
        const float4* sr = (const float4*)(h + (size_t)s * F);
        #pragma unroll
        for (int v = 0; v < V; v++) {
            float4 t = sr[lane + 32 * v];
            acc[v].x += w * t.x; acc[v].y += w * t.y;
            acc[v].z += w * t.z; acc[v].w += w * t.w;
        }
    }

    const float4* bv = (const float4*)bias;
    float4* ov = (float4*)(out + (size_t)node * F);
    #pragma unroll
    for (int v = 0; v < V; v++) {
        float4 b = bv[lane + 32 * v];
        float4 o = make_float4(acc[v].x + b.x, acc[v].y + b.y,
                               acc[v].z + b.z, acc[v].w + b.w);
        if (LAYER == 0) {
            o.x = fmaxf(o.x, 0.f); o.y = fmaxf(o.y, 0.f);
            o.z = fmaxf(o.z, 0.f); o.w = fmaxf(o.w, 0.f);
        }
        ov[lane + 32 * v] = o;
    }
}

// ---------------------------------------------------------------------------
// launch — inputs identified by element count (order-proof)
// ---------------------------------------------------------------------------
extern "C" void kernel_launch(void* const* d_in, const int* in_sizes, int n_in,
                              void* d_out, int out_size) {
    const float* x  = nullptr;
    const void*  ei = nullptr;
    const float* W1 = nullptr;
    const float* b1 = nullptr;
    const float* W2 = nullptr;
    const float* b2 = nullptr;

    for (int i = 0; i < n_in; i++) {
        switch (in_sizes[i]) {
            case NN * FIN:   x  = (const float*)d_in[i]; break;
            case 2 * NE:     ei = d_in[i];               break;
            case FIN * FH:   W1 = (const float*)d_in[i]; break;
            case FH:         b1 = (const float*)d_in[i]; break;
            case FH * FO:    W2 = (const float*)d_in[i]; break;
            case FO:         b2 = (const float*)d_in[i]; break;
            default: break;
        }
    }
    float* out = (float*)d_out;

    static bool attr_set = false;
    if (!attr_set) {
        cudaFuncSetAttribute(mma_gemm,
                             cudaFuncAttributeMaxDynamicSharedMemorySize,
                             SMEM_TOTAL);
        attr_set = true;
    }

    const int T = 256;
    const int NBLK = (NN + 255) / 256;   // 196

    k_detect   <<<1, 32>>>(ei);
    k_init     <<<(NN + T - 1) / T, T>>>();
    k_deg_count<<<(NE + T - 1) / T, T>>>(ei);
    k_dinv     <<<(NN + T - 1) / T, T>>>();
    k_scan1    <<<NBLK, 256>>>();
    k_scan2    <<<1, 256>>>(NBLK);
    k_scan3    <<<NBLK, 256>>>();
    k_fill     <<<(NE + T - 1) / T, T>>>(ei);

    // layer 1: h1 = x @ W1
    k_conv_b<<<(FIN * FH + T - 1) / T, T>>>(W1, FIN, FH);
    {
        dim3 grid(FH / 128, (NN + 127) / 128);
        mma_gemm<<<grid, 256, SMEM_TOTAL>>>(x, 0, NN, FH, FIN);
    }
    k_gather<0><<<((size_t)NN * 32 + T - 1) / T, T>>>(b1, nullptr);

    // layer 2: h2 = agg1 @ W2
    k_conv_b<<<(FH * FO + T - 1) / T, T>>>(W2, FH, FO);
    {
        dim3 grid(FO / 128, (NN + 127) / 128);
        mma_gemm<<<grid, 256, SMEM_TOTAL>>>(nullptr, 1, NN, FO, FH);
    }
    k_gather<1><<<((size_t)NN * 32 + T - 1) / T, T>>>(b2, out);
}

// round 13
// speedup vs baseline: 2.1606x; 1.0781x over previous
#include <cuda_runtime.h>
#include <cuda_fp16.h>
#include <stdint.h>

#define NN  50000
#define NE  800000
#define FIN 512
#define FH  256
#define FO  128

// ---- scratch: __device__ globals ----
__device__ int   g_is64;
__device__ __align__(16) float g_dinv[NN];
__device__ __align__(16) int   g_cnt [NN];
__device__ __align__(16) int   g_off [NN + 1];
__device__ __align__(16) int   g_fill[NN];
__device__ __align__(16) int   g_blk [256];
__device__ __align__(16) int   g_csr_src[NE];
__device__ __align__(16) float g_csr_w  [NE];
__device__ __align__(16) __half g_h1  [(size_t)NN * FH];   // fp16 activations
__device__ __align__(16) float  g_agg1[(size_t)NN * FH];   // fp32 (feeds exact split)
__device__ __align__(16) __half g_h2  [(size_t)NN * FO];
__device__ __align__(16) __half g_Bh[(size_t)FH * FIN];    // B^T fp16

// ---------------------------------------------------------------------------
// edge dtype detect (parallel) + decode
// ---------------------------------------------------------------------------
__global__ void k_detect(const void* __restrict__ ei) {
    const long long* p = (const long long*)ei;
    int lane = threadIdx.x;
    int bad = 0;
    #pragma unroll 4
    for (int i = lane; i < 2048; i += 32) {
        long long v = p[i];
        if (v < 0 || v >= NN) bad = 1;
    }
    unsigned m = __ballot_sync(0xffffffffu, bad);
    if (lane == 0) g_is64 = (m == 0);
}

__device__ __forceinline__ unsigned eidx(const void* __restrict__ ei, size_t idx) {
    if (g_is64) return (unsigned)((const long long*)ei)[idx];
    return (unsigned)((const int*)ei)[idx];
}

// ---------------------------------------------------------------------------
// degree / normalization / CSR build
// ---------------------------------------------------------------------------
__global__ void k_init() {
    int i = blockIdx.x * blockDim.x + threadIdx.x;
    if (i < NN) { g_cnt[i] = 0; g_fill[i] = 0; }
}

__global__ void k_deg_count(const void* __restrict__ ei) {
    int i = blockIdx.x * blockDim.x + threadIdx.x;
    if (i < NE) {
        unsigned d = eidx(ei, (size_t)NE + i);
        if (d < NN) atomicAdd(&g_cnt[d], 1);
    }
}

__global__ void k_dinv() {
    int i = blockIdx.x * blockDim.x + threadIdx.x;
    if (i < NN) g_dinv[i] = rsqrtf((float)(g_cnt[i] + 1));
}

// ---- 3-phase parallel exclusive scan of g_cnt -> g_off ----
__global__ void k_scan1() {
    __shared__ int wsum[8];
    int i = blockIdx.x * 256 + threadIdx.x;
    int lane = threadIdx.x & 31, wid = threadIdx.x >> 5;
    int v = (i < NN) ? g_cnt[i] : 0;
    int s = v;
    #pragma unroll
    for (int o = 1; o < 32; o <<= 1) {
        int t = __shfl_up_sync(0xffffffffu, s, o);
        if (lane >= o) s += t;
    }
    if (lane == 31) wsum[wid] = s;
    __syncthreads();
    if (wid == 0 && lane < 8) {
        int w = wsum[lane];
        #pragma unroll
        for (int o = 1; o < 8; o <<= 1) {
            int t = __shfl_up_sync(0xffu, w, o);
            if (lane >= o) w += t;
        }
        wsum[lane] = w;
    }
    __syncthreads();
    int woff = (wid == 0) ? 0 : wsum[wid - 1];
    if (i < NN) g_off[i] = woff + s - v;
    if (threadIdx.x == 255) g_blk[blockIdx.x] = woff + s;
}

__global__ void k_scan2(int nblk) {
    __shared__ int wsum[8];
    int lane = threadIdx.x & 31, wid = threadIdx.x >> 5;
    int v = (threadIdx.x < nblk) ? g_blk[threadIdx.x] : 0;
    int s = v;
    #pragma unroll
    for (int o = 1; o < 32; o <<= 1) {
        int t = __shfl_up_sync(0xffffffffu, s, o);
        if (lane >= o) s += t;
    }
    if (lane == 31) wsum[wid] = s;
    __syncthreads();
    if (wid == 0 && lane < 8) {
        int w = wsum[lane];
        #pragma unroll
        for (int o = 1; o < 8; o <<= 1) {
            int t = __shfl_up_sync(0xffu, w, o);
            if (lane >= o) w += t;
        }
        wsum[lane] = w;
    }
    __syncthreads();
    int woff = (wid == 0) ? 0 : wsum[wid - 1];
    if (threadIdx.x < nblk) g_blk[threadIdx.x] = woff + s - v;
    if (threadIdx.x == 255) g_off[NN] = woff + s;
}

__global__ void k_scan3() {
    int i = blockIdx.x * 256 + threadIdx.x;
    if (i < NN) g_off[i] += g_blk[i >> 8];
}

__global__ void k_fill(const void* __restrict__ ei) {
    int i = blockIdx.x * blockDim.x + threadIdx.x;
    if (i < NE) {
        unsigned s = eidx(ei, i);
        unsigned d = eidx(ei, (size_t)NE + i);
        if (s < NN && d < NN) {
            int pos = g_off[d] + atomicAdd(&g_fill[d], 1);
            if (pos < NE) {
                g_csr_src[pos] = (int)s;
                g_csr_w[pos]   = g_dinv[s] * g_dinv[d];
            }
        }
    }
}

// ---------------------------------------------------------------------------
// B convert: W [K][N] fp32 -> g_Bh [N][K] fp16 (transposed)
// ---------------------------------------------------------------------------
__global__ void k_conv_b(const float* __restrict__ W, int K, int N) {
    int i = blockIdx.x * blockDim.x + threadIdx.x;
    if (i >= K * N) return;
    int k = i / N, n = i % N;
    g_Bh[(size_t)n * K + k] = __float2half(W[i]);
}

// ---------------------------------------------------------------------------
// fp16 split-mma GEMM with cp.async double buffering; fp16 C output.
// C[M,N](fp16) = A[M,K](fp32) @ B[N,K](fp16)^T, fp32 accum, A split hi+lo.
// ---------------------------------------------------------------------------
#define SRH 40
#define SRF 36
#define SZ_STAGEA (128 * SRF * 4)
#define SZ_HTILE  (128 * SRH * 2)
#define OFF_STAGEA 0
#define OFF_BS  (2 * SZ_STAGEA)
#define OFF_AH  (OFF_BS + 2 * SZ_HTILE)
#define OFF_AL  (OFF_AH + 2 * SZ_HTILE)
#define SMEM_TOTAL (OFF_AL + 2 * SZ_HTILE)   // 98304

#define LDSM_X4(r0, r1, r2, r3, addr)                                        \
    asm volatile("ldmatrix.sync.aligned.m8n8.x4.shared.b16 {%0,%1,%2,%3}, [%4];" \
                 : "=r"(r0), "=r"(r1), "=r"(r2), "=r"(r3) : "r"(addr))

__device__ __forceinline__ void cp16(uint32_t dst, const void* src, int srcsz) {
    asm volatile("cp.async.cg.shared.global [%0], [%1], 16, %2;"
                 :: "r"(dst), "l"(src), "r"(srcsz));
}

__global__ void __launch_bounds__(256)
mma_gemm(const float* __restrict__ Aext, int layer, int M, int N, int K) {
    const float*  A = (layer == 0) ? Aext : (const float*)g_agg1;
    __half*       C = (layer == 0) ? g_h1 : g_h2;
    const __half* B = g_Bh;

    extern __shared__ __align__(16) char dyn[];
    const uint32_t sbase = (uint32_t)__cvta_generic_to_shared(dyn);

    const int tid  = threadIdx.x;
    const int lane = tid & 31;
    const int wid  = tid >> 5;
    const int wm   = wid >> 2;
    const int wn   = wid & 3;
    const int row0 = blockIdx.y * 128;
    const int col0 = blockIdx.x * 128;

    const int ldr = tid >> 1;
    const int ldc = (tid & 1) * 16;

    const int gm = row0 + ldr;
    const int gn = col0 + ldr;
    const int a_ok = (gm < M) ? 16 : 0;
    const float*  a_base = A + (size_t)gm * K + ldc;
    const __half* b_base = B + (size_t)gn * K + ldc;
    const uint32_t da = sbase + OFF_STAGEA + (uint32_t)((ldr * SRF + ldc) * 4);
    const uint32_t db = sbase + OFF_BS     + (uint32_t)((ldr * SRH + ldc) * 2);

    float acc[4][4][4];
    #pragma unroll
    for (int mi = 0; mi < 4; mi++)
        #pragma unroll
        for (int ni = 0; ni < 4; ni++)
            #pragma unroll
            for (int q = 0; q < 4; q++) acc[mi][ni][q] = 0.f;

    const int a_row  = (lane & 15);
    const int a_colh = (lane >> 4) * 8;
    const int b_row  = (lane >> 4) * 8 + (lane & 7);
    const int b_colh = ((lane >> 3) & 1) * 8;

    const int NC = K >> 5;

    {
        #pragma unroll
        for (int j = 0; j < 4; j++) cp16(da + j * 16, a_base + j * 4, a_ok);
        #pragma unroll
        for (int j = 0; j < 2; j++) cp16(db + j * 16, b_base + j * 8, 16);
        asm volatile("cp.async.commit_group;");
    }

    int buf = 0;
    for (int c = 0; c < NC; c++) {
        asm volatile("cp.async.wait_group 0;");
        __syncthreads();

        if (c + 1 < NC) {
            int k0 = (c + 1) * 32;
            uint32_t da2 = da + (buf ^ 1) * SZ_STAGEA;
            uint32_t db2 = db + (buf ^ 1) * SZ_HTILE;
            #pragma unroll
            for (int j = 0; j < 4; j++) cp16(da2 + j * 16, a_base + k0 + j * 4, a_ok);
            #pragma unroll
            for (int j = 0; j < 2; j++) cp16(db2 + j * 16, b_base + k0 + j * 8, 16);
            asm volatile("cp.async.commit_group;");
        }

        {
            const float4* src = (const float4*)(dyn + OFF_STAGEA + buf * SZ_STAGEA
                                                + (ldr * SRF + ldc) * 4);
            __half2* hh = (__half2*)(dyn + OFF_AH + buf * SZ_HTILE
                                     + (ldr * SRH + ldc) * 2);
            __half2* hl = (__half2*)(dyn + OFF_AL + buf * SZ_HTILE
                                     + (ldr * SRH + ldc) * 2);
            #pragma unroll
            for (int j = 0; j < 4; j++) {
                float4 v = src[j];
                __half hx = __float2half(v.x), hy = __float2half(v.y);
                __half hz = __float2half(v.z), hw = __float2half(v.w);
                hh[2 * j]     = __halves2half2(hx, hy);
                hh[2 * j + 1] = __halves2half2(hz, hw);
                hl[2 * j]     = __halves2half2(__float2half(v.x - __half2float(hx)),
                                               __float2half(v.y - __half2float(hy)));
                hl[2 * j + 1] = __halves2half2(__float2half(v.z - __half2float(hz)),
                                               __float2half(v.w - __half2float(hw)));
            }
        }
        __syncthreads();

        const uint32_t sAh = sbase + OFF_AH + buf * SZ_HTILE;
        const uint32_t sAl = sbase + OFF_AL + buf * SZ_HTILE;
        const uint32_t sB  = sbase + OFF_BS + buf * SZ_HTILE;

        #pragma unroll
        for (int kk = 0; kk < 2; kk++) {
            const int kh = kk * 16;
            uint32_t bfr[4][2];
            #pragma unroll
            for (int nip = 0; nip < 2; nip++) {
                uint32_t addr = sB +
                    (uint32_t)(((wn * 32 + nip * 16 + b_row) * SRH + kh + b_colh) * 2);
                LDSM_X4(bfr[2 * nip][0], bfr[2 * nip][1],
                        bfr[2 * nip + 1][0], bfr[2 * nip + 1][1], addr);
            }
            #pragma unroll
            for (int part = 0; part < 2; part++) {
                const uint32_t sA = part ? sAl : sAh;
                uint32_t afr[4][4];
                #pragma unroll
                for (int mi = 0; mi < 4; mi++) {
                    uint32_t addr = sA +
                        (uint32_t)(((wm * 64 + mi * 16 + a_row) * SRH + kh + a_colh) * 2);
                    LDSM_X4(afr[mi][0], afr[mi][1], afr[mi][2], afr[mi][3], addr);
                }
                #pragma unroll
                for (int mi = 0; mi < 4; mi++)
                    #pragma unroll
                    for (int ni = 0; ni < 4; ni++) {
                        asm volatile(
                            "mma.sync.aligned.m16n8k16.row.col.f32.f16.f16.f32 "
                            "{%0,%1,%2,%3}, {%4,%5,%6,%7}, {%8,%9}, {%0,%1,%2,%3};"
                            : "+f"(acc[mi][ni][0]), "+f"(acc[mi][ni][1]),
                              "+f"(acc[mi][ni][2]), "+f"(acc[mi][ni][3])
                            : "r"(afr[mi][0]), "r"(afr[mi][1]),
                              "r"(afr[mi][2]), "r"(afr[mi][3]),
                              "r"(bfr[ni][0]), "r"(bfr[ni][1]));
                    }
            }
        }
        buf ^= 1;
    }

    // epilogue: fp16 store (half2 per register pair)
    const int lr = lane >> 2, lc = lane & 3;
    #pragma unroll
    for (int mi = 0; mi < 4; mi++) {
        int r0 = row0 + wm * 64 + mi * 16 + lr;
        int r1 = r0 + 8;
        #pragma unroll
        for (int ni = 0; ni < 4; ni++) {
            int cb = col0 + wn * 32 + ni * 8 + lc * 2;
            if (r0 < M)
                *(__half2*)&C[(size_t)r0 * N + cb] =
                    __floats2half2_rn(acc[mi][ni][0], acc[mi][ni][1]);
            if (r1 < M)
                *(__half2*)&C[(size_t)r1 * N + cb] =
                    __floats2half2_rn(acc[mi][ni][2], acc[mi][ni][3]);
        }
    }
}

// ---------------------------------------------------------------------------
// CSR gather (fp16 h): out[i,:] = dinv^2*h[i,:] + sum_e w_e*h[src_e,:] + bias
// LAYER 0: F=256, lane owns 8 cols (uint4 = 8 halfs), out fp32 agg1, ReLU
// LAYER 1: F=128, lane owns 4 cols (uint2 = 4 halfs), out fp32 d_out
// ---------------------------------------------------------------------------
template<int LAYER>
__global__ void k_gather(const float* __restrict__ bias,
                         float* __restrict__ outext) {
    constexpr int F = (LAYER == 0) ? FH : FO;
    constexpr int H = F / 32;              // halfs per lane: 8 or 4
    const __half* h   = (LAYER == 0) ? (const __half*)g_h1 : (const __half*)g_h2;
    float*        out = (LAYER == 0) ? g_agg1 : outext;

    int node = (blockIdx.x * blockDim.x + threadIdx.x) >> 5;
    int lane = threadIdx.x & 31;
    if (node >= NN) return;

    float acc[H];
    float wi = g_dinv[node];
    wi *= wi;

    // self term
    {
        const __half2* p = (const __half2*)(h + (size_t)node * F + lane * H);
        #pragma unroll
        for (int j = 0; j < H / 2; j++) {
            float2 f = __half22float2(p[j]);
            acc[2 * j]     = wi * f.x;
            acc[2 * j + 1] = wi * f.y;
        }
    }

    int beg = g_off[node];
    int end = beg + g_cnt[node];
    for (int e = beg; e < end; e++) {
        int   s = g_csr_src[e];
        float w = g_csr_w[e];
        const __half* sp = h + (size_t)s * F + lane * H;
        if (H == 8) {
            uint4 raw = *(const uint4*)sp;
            const __half2* v = (const __half2*)&raw;
            #pragma unroll
            for (int j = 0; j < 4; j++) {
                float2 f = __half22float2(v[j]);
                acc[2 * j]     += w * f.x;
                acc[2 * j + 1] += w * f.y;
            }
        } else {
            uint2 raw = *(const uint2*)sp;
            const __half2* v = (const __half2*)&raw;
            #pragma unroll
            for (int j = 0; j < 2; j++) {
                float2 f = __half22float2(v[j]);
                acc[2 * j]     += w * f.x;
                acc[2 * j + 1] += w * f.y;
            }
        }
    }

    // bias + (ReLU) + store fp32
    const float* bp = bias + lane * H;
    float* op = out + (size_t)node * F + lane * H;
    #pragma unroll
    for (int j = 0; j < H / 4; j++) {
        float4 b = *(const float4*)(bp + 4 * j);
        float4 o = make_float4(acc[4 * j] + b.x,     acc[4 * j + 1] + b.y,
                               acc[4 * j + 2] + b.z, acc[4 * j + 3] + b.w);
        if (LAYER == 0) {
            o.x = fmaxf(o.x, 0.f); o.y = fmaxf(o.y, 0.f);
            o.z = fmaxf(o.z, 0.f); o.w = fmaxf(o.w, 0.f);
        }
        *(float4*)(op + 4 * j) = o;
    }
}

// ---------------------------------------------------------------------------
// launch
// ---------------------------------------------------------------------------
extern "C" void kernel_launch(void* const* d_in, const int* in_sizes, int n_in,
                              void* d_out, int out_size) {
    const float* x  = nullptr;
    const void*  ei = nullptr;
    const float* W1 = nullptr;
    const float* b1 = nullptr;
    const float* W2 = nullptr;
    const float* b2 = nullptr;

    for (int i = 0; i < n_in; i++) {
        switch (in_sizes[i]) {
            case NN * FIN:   x  = (const float*)d_in[i]; break;
            case 2 * NE:     ei = d_in[i];               break;
            case FIN * FH:   W1 = (const float*)d_in[i]; break;
            case FH:         b1 = (const float*)d_in[i]; break;
            case FH * FO:    W2 = (const float*)d_in[i]; break;
            case FO:         b2 = (const float*)d_in[i]; break;
            default: break;
        }
    }
    float* out = (float*)d_out;

    static bool attr_set = false;
    if (!attr_set) {
        cudaFuncSetAttribute(mma_gemm,
                             cudaFuncAttributeMaxDynamicSharedMemorySize,
                             SMEM_TOTAL);
        attr_set = true;
    }

    const int T = 256;
    const int NBLK = (NN + 255) / 256;

    k_detect   <<<1, 32>>>(ei);
    k_init     <<<(NN + T - 1) / T, T>>>();
    k_deg_count<<<(NE + T - 1) / T, T>>>(ei);
    k_dinv     <<<(NN + T - 1) / T, T>>>();
    k_scan1    <<<NBLK, 256>>>();
    k_scan2    <<<1, 256>>>(NBLK);
    k_scan3    <<<NBLK, 256>>>();
    k_fill     <<<(NE + T - 1) / T, T>>>(ei);

    // layer 1
    k_conv_b<<<(FIN * FH + T - 1) / T, T>>>(W1, FIN, FH);
    {
        dim3 grid(FH / 128, (NN + 127) / 128);
        mma_gemm<<<grid, 256, SMEM_TOTAL>>>(x, 0, NN, FH, FIN);
    }
    k_gather<0><<<((size_t)NN * 32 + T - 1) / T, T>>>(b1, nullptr);

    // layer 2
    k_conv_b<<<(FH * FO + T - 1) / T, T>>>(W2, FH, FO);
    {
        dim3 grid(FO / 128, (NN + 127) / 128);
        mma_gemm<<<grid, 256, SMEM_TOTAL>>>(nullptr, 1, NN, FO, FH);
    }
    k_gather<1><<<((size_t)NN * 32 + T - 1) / T, T>>>(b2, out);
}

// round 15
// speedup vs baseline: 2.4175x; 1.1189x over previous
#include <cuda_runtime.h>
#include <cuda_fp16.h>
#include <stdint.h>

#define NN  50000
#define NE  800000
#define FIN 512
#define FH  256
#define FO  128

// ---- scratch: __device__ globals ----
__device__ int   g_is64;
__device__ __align__(16) float g_dinv[NN];
__device__ __align__(16) int   g_cnt [NN];
__device__ __align__(16) int   g_off [NN + 1];
__device__ __align__(16) int   g_fill[NN];
__device__ __align__(16) int   g_blk [256];
__device__ __align__(16) int   g_csr_src[NE];
__device__ __align__(16) float g_csr_w  [NE];
__device__ __align__(16) __half g_h1  [(size_t)NN * FH];   // fp16 activations
__device__ __align__(16) float  g_agg1[(size_t)NN * FH];   // fp32 (feeds exact split)
__device__ __align__(16) __half g_h2  [(size_t)NN * FO];
__device__ __align__(16) __half g_Bh [(size_t)FH * FIN];   // W1^T fp16
__device__ __align__(16) __half g_Bh2[(size_t)FO * FH];    // W2^T fp16

// ---------------------------------------------------------------------------
// edge dtype detect (parallel) + decode
// ---------------------------------------------------------------------------
__global__ void k_detect(const void* __restrict__ ei) {
    const long long* p = (const long long*)ei;
    int lane = threadIdx.x;
    int bad = 0;
    #pragma unroll 4
    for (int i = lane; i < 2048; i += 32) {
        long long v = p[i];
        if (v < 0 || v >= NN) bad = 1;
    }
    unsigned m = __ballot_sync(0xffffffffu, bad);
    if (lane == 0) g_is64 = (m == 0);
}

__device__ __forceinline__ unsigned eidx(const void* __restrict__ ei, size_t idx) {
    if (g_is64) return (unsigned)((const long long*)ei)[idx];
    return (unsigned)((const int*)ei)[idx];
}

// ---------------------------------------------------------------------------
// degree / normalization / CSR build
// ---------------------------------------------------------------------------
__global__ void k_init() {
    int i = blockIdx.x * blockDim.x + threadIdx.x;
    if (i < NN) { g_cnt[i] = 0; g_fill[i] = 0; }
}

__global__ void k_deg_count(const void* __restrict__ ei) {
    int i = blockIdx.x * blockDim.x + threadIdx.x;
    if (i < NE) {
        unsigned d = eidx(ei, (size_t)NE + i);
        if (d < NN) atomicAdd(&g_cnt[d], 1);
    }
}

__global__ void k_dinv() {
    int i = blockIdx.x * blockDim.x + threadIdx.x;
    if (i < NN) g_dinv[i] = rsqrtf((float)(g_cnt[i] + 1));
}

__global__ void k_scan1() {
    __shared__ int wsum[8];
    int i = blockIdx.x * 256 + threadIdx.x;
    int lane = threadIdx.x & 31, wid = threadIdx.x >> 5;
    int v = (i < NN) ? g_cnt[i] : 0;
    int s = v;
    #pragma unroll
    for (int o = 1; o < 32; o <<= 1) {
        int t = __shfl_up_sync(0xffffffffu, s, o);
        if (lane >= o) s += t;
    }
    if (lane == 31) wsum[wid] = s;
    __syncthreads();
    if (wid == 0 && lane < 8) {
        int w = wsum[lane];
        #pragma unroll
        for (int o = 1; o < 8; o <<= 1) {
            int t = __shfl_up_sync(0xffu, w, o);
            if (lane >= o) w += t;
        }
        wsum[lane] = w;
    }
    __syncthreads();
    int woff = (wid == 0) ? 0 : wsum[wid - 1];
    if (i < NN) g_off[i] = woff + s - v;
    if (threadIdx.x == 255) g_blk[blockIdx.x] = woff + s;
}

__global__ void k_scan2(int nblk) {
    __shared__ int wsum[8];
    int lane = threadIdx.x & 31, wid = threadIdx.x >> 5;
    int v = (threadIdx.x < nblk) ? g_blk[threadIdx.x] : 0;
    int s = v;
    #pragma unroll
    for (int o = 1; o < 32; o <<= 1) {
        int t = __shfl_up_sync(0xffffffffu, s, o);
        if (lane >= o) s += t;
    }
    if (lane == 31) wsum[wid] = s;
    __syncthreads();
    if (wid == 0 && lane < 8) {
        int w = wsum[lane];
        #pragma unroll
        for (int o = 1; o < 8; o <<= 1) {
            int t = __shfl_up_sync(0xffu, w, o);
            if (lane >= o) w += t;
        }
        wsum[lane] = w;
    }
    __syncthreads();
    int woff = (wid == 0) ? 0 : wsum[wid - 1];
    if (threadIdx.x < nblk) g_blk[threadIdx.x] = woff + s - v;
    if (threadIdx.x == 255) g_off[NN] = woff + s;
}

__global__ void k_scan3() {
    int i = blockIdx.x * 256 + threadIdx.x;
    if (i < NN) g_off[i] += g_blk[i >> 8];
}

__global__ void k_fill(const void* __restrict__ ei) {
    int i = blockIdx.x * blockDim.x + threadIdx.x;
    if (i < NE) {
        unsigned s = eidx(ei, i);
        unsigned d = eidx(ei, (size_t)NE + i);
        if (s < NN && d < NN) {
            int pos = g_off[d] + atomicAdd(&g_fill[d], 1);
            if (pos < NE) {
                g_csr_src[pos] = (int)s;
                g_csr_w[pos]   = g_dinv[s] * g_dinv[d];
            }
        }
    }
}

// ---------------------------------------------------------------------------
// B convert: W [K][N] fp32 -> [N][K] fp16 (transposed); buffer per layer
// ---------------------------------------------------------------------------
__global__ void k_conv_b(const float* __restrict__ W, int layer, int K, int N) {
    __half* dst = (layer == 0) ? g_Bh : g_Bh2;
    int i = blockIdx.x * blockDim.x + threadIdx.x;
    if (i >= K * N) return;
    int k = i / N, n = i % N;
    dst[(size_t)n * K + k] = __float2half(W[i]);
}

// ---------------------------------------------------------------------------
// fp16 split-mma GEMM with cp.async double buffering; fp16 C output.
// C[M,N](fp16) = A[M,K](fp32) @ B[N,K](fp16)^T, fp32 accum, A split hi+lo.
// ---------------------------------------------------------------------------
#define SRH 40
#define SRF 36
#define SZ_STAGEA (128 * SRF * 4)
#define SZ_HTILE  (128 * SRH * 2)
#define OFF_STAGEA 0
#define OFF_BS  (2 * SZ_STAGEA)
#define OFF_AH  (OFF_BS + 2 * SZ_HTILE)
#define OFF_AL  (OFF_AH + 2 * SZ_HTILE)
#define SMEM_TOTAL (OFF_AL + 2 * SZ_HTILE)   // 98304

#define LDSM_X4(r0, r1, r2, r3, addr)                                        \
    asm volatile("ldmatrix.sync.aligned.m8n8.x4.shared.b16 {%0,%1,%2,%3}, [%4];" \
                 : "=r"(r0), "=r"(r1), "=r"(r2), "=r"(r3) : "r"(addr))

__device__ __forceinline__ void cp16(uint32_t dst, const void* src, int srcsz) {
    asm volatile("cp.async.cg.shared.global [%0], [%1], 16, %2;"
                 :: "r"(dst), "l"(src), "r"(srcsz));
}

__global__ void __launch_bounds__(256)
mma_gemm(const float* __restrict__ Aext, int layer, int M, int N, int K) {
    const float*  A = (layer == 0) ? Aext : (const float*)g_agg1;
    __half*       C = (layer == 0) ? g_h1 : g_h2;
    const __half* B = (layer == 0) ? g_Bh : g_Bh2;

    extern __shared__ __align__(16) char dyn[];
    const uint32_t sbase = (uint32_t)__cvta_generic_to_shared(dyn);

    const int tid  = threadIdx.x;
    const int lane = tid & 31;
    const int wid  = tid >> 5;
    const int wm   = wid >> 2;
    const int wn   = wid & 3;
    const int row0 = blockIdx.y * 128;
    const int col0 = blockIdx.x * 128;

    const int ldr = tid >> 1;
    const int ldc = (tid & 1) * 16;

    const int gm = row0 + ldr;
    const int gn = col0 + ldr;
    const int a_ok = (gm < M) ? 16 : 0;
    const float*  a_base = A + (size_t)gm * K + ldc;
    const __half* b_base = B + (size_t)gn * K + ldc;
    const uint32_t da = sbase + OFF_STAGEA + (uint32_t)((ldr * SRF + ldc) * 4);
    const uint32_t db = sbase + OFF_BS     + (uint32_t)((ldr * SRH + ldc) * 2);

    float acc[4][4][4];
    #pragma unroll
    for (int mi = 0; mi < 4; mi++)
        #pragma unroll
        for (int ni = 0; ni < 4; ni++)
            #pragma unroll
            for (int q = 0; q < 4; q++) acc[mi][ni][q] = 0.f;

    const int a_row  = (lane & 15);
    const int a_colh = (lane >> 4) * 8;
    const int b_row  = (lane >> 4) * 8 + (lane & 7);
    const int b_colh = ((lane >> 3) & 1) * 8;

    const int NC = K >> 5;

    {
        #pragma unroll
        for (int j = 0; j < 4; j++) cp16(da + j * 16, a_base + j * 4, a_ok);
        #pragma unroll
        for (int j = 0; j < 2; j++) cp16(db + j * 16, b_base + j * 8, 16);
        asm volatile("cp.async.commit_group;");
    }

    int buf = 0;
    for (int c = 0; c < NC; c++) {
        asm volatile("cp.async.wait_group 0;");
        __syncthreads();

        if (c + 1 < NC) {
            int k0 = (c + 1) * 32;
            uint32_t da2 = da + (buf ^ 1) * SZ_STAGEA;
            uint32_t db2 = db + (buf ^ 1) * SZ_HTILE;
            #pragma unroll
            for (int j = 0; j < 4; j++) cp16(da2 + j * 16, a_base + k0 + j * 4, a_ok);
            #pragma unroll
            for (int j = 0; j < 2; j++) cp16(db2 + j * 16, b_base + k0 + j * 8, 16);
            asm volatile("cp.async.commit_group;");
        }

        {
            const float4* src = (const float4*)(dyn + OFF_STAGEA + buf * SZ_STAGEA
                                                + (ldr * SRF + ldc) * 4);
            __half2* hh = (__half2*)(dyn + OFF_AH + buf * SZ_HTILE
                                     + (ldr * SRH + ldc) * 2);
            __half2* hl = (__half2*)(dyn + OFF_AL + buf * SZ_HTILE
                                     + (ldr * SRH + ldc) * 2);
            #pragma unroll
            for (int j = 0; j < 4; j++) {
                float4 v = src[j];
                __half hx = __float2half(v.x), hy = __float2half(v.y);
                __half hz = __float2half(v.z), hw = __float2half(v.w);
                hh[2 * j]     = __halves2half2(hx, hy);
                hh[2 * j + 1] = __halves2half2(hz, hw);
                hl[2 * j]     = __halves2half2(__float2half(v.x - __half2float(hx)),
                                               __float2half(v.y - __half2float(hy)));
                hl[2 * j + 1] = __halves2half2(__float2half(v.z - __half2float(hz)),
                                               __float2half(v.w - __half2float(hw)));
            }
        }
        __syncthreads();

        const uint32_t sAh = sbase + OFF_AH + buf * SZ_HTILE;
        const uint32_t sAl = sbase + OFF_AL + buf * SZ_HTILE;
        const uint32_t sB  = sbase + OFF_BS + buf * SZ_HTILE;

        #pragma unroll
        for (int kk = 0; kk < 2; kk++) {
            const int kh = kk * 16;
            uint32_t bfr[4][2];
            #pragma unroll
            for (int nip = 0; nip < 2; nip++) {
                uint32_t addr = sB +
                    (uint32_t)(((wn * 32 + nip * 16 + b_row) * SRH + kh + b_colh) * 2);
                LDSM_X4(bfr[2 * nip][0], bfr[2 * nip][1],
                        bfr[2 * nip + 1][0], bfr[2 * nip + 1][1], addr);
            }
            #pragma unroll
            for (int part = 0; part < 2; part++) {
                const uint32_t sA = part ? sAl : sAh;
                uint32_t afr[4][4];
                #pragma unroll
                for (int mi = 0; mi < 4; mi++) {
                    uint32_t addr = sA +
                        (uint32_t)(((wm * 64 + mi * 16 + a_row) * SRH + kh + a_colh) * 2);
                    LDSM_X4(afr[mi][0], afr[mi][1], afr[mi][2], afr[mi][3], addr);
                }
                #pragma unroll
                for (int mi = 0; mi < 4; mi++)
                    #pragma unroll
                    for (int ni = 0; ni < 4; ni++) {
                        asm volatile(
                            "mma.sync.aligned.m16n8k16.row.col.f32.f16.f16.f32 "
                            "{%0,%1,%2,%3}, {%4,%5,%6,%7}, {%8,%9}, {%0,%1,%2,%3};"
                            : "+f"(acc[mi][ni][0]), "+f"(acc[mi][ni][1]),
                              "+f"(acc[mi][ni][2]), "+f"(acc[mi][ni][3])
                            : "r"(afr[mi][0]), "r"(afr[mi][1]),
                              "r"(afr[mi][2]), "r"(afr[mi][3]),
                              "r"(bfr[ni][0]), "r"(bfr[ni][1]));
                    }
            }
        }
        buf ^= 1;
    }

    const int lr = lane >> 2, lc = lane & 3;
    #pragma unroll
    for (int mi = 0; mi < 4; mi++) {
        int r0 = row0 + wm * 64 + mi * 16 + lr;
        int r1 = r0 + 8;
        #pragma unroll
        for (int ni = 0; ni < 4; ni++) {
            int cb = col0 + wn * 32 + ni * 8 + lc * 2;
            if (r0 < M)
                *(__half2*)&C[(size_t)r0 * N + cb] =
                    __floats2half2_rn(acc[mi][ni][0], acc[mi][ni][1]);
            if (r1 < M)
                *(__half2*)&C[(size_t)r1 * N + cb] =
                    __floats2half2_rn(acc[mi][ni][2], acc[mi][ni][3]);
        }
    }
}

// ---------------------------------------------------------------------------
// CSR gather (fp16 h), edge loop unrolled x2 for MLP.
// ---------------------------------------------------------------------------
template<int LAYER>
__global__ void k_gather(const float* __restrict__ bias,
                         float* __restrict__ outext) {
    constexpr int F = (LAYER == 0) ? FH : FO;
    constexpr int H = F / 32;
    const __half* h   = (LAYER == 0) ? (const __half*)g_h1 : (const __half*)g_h2;
    float*        out = (LAYER == 0) ? g_agg1 : outext;

    int node = (blockIdx.x * blockDim.x + threadIdx.x) >> 5;
    int lane = threadIdx.x & 31;
    if (node >= NN) return;

    float acc[H];
    float wi = g_dinv[node];
    wi *= wi;

    {
        const __half2* p = (const __half2*)(h + (size_t)node * F + lane * H);
        #pragma unroll
        for (int j = 0; j < H / 2; j++) {
            float2 f = __half22float2(p[j]);
            acc[2 * j]     = wi * f.x;
            acc[2 * j + 1] = wi * f.y;
        }
    }

    int beg = g_off[node];
    int end = beg + g_cnt[node];
    int e = beg;
    for (; e + 2 <= end; e += 2) {
        int   s0 = g_csr_src[e],     s1 = g_csr_src[e + 1];
        float w0 = g_csr_w[e],       w1 = g_csr_w[e + 1];
        const __half* p0 = h + (size_t)s0 * F + lane * H;
        const __half* p1 = h + (size_t)s1 * F + lane * H;
        if (H == 8) {
            uint4 r0 = *(const uint4*)p0;
            uint4 r1 = *(const uint4*)p1;
            const __half2* v0 = (const __half2*)&r0;
            const __half2* v1 = (const __half2*)&r1;
            #pragma unroll
            for (int j = 0; j < 4; j++) {
                float2 f0 = __half22float2(v0[j]);
                float2 f1 = __half22float2(v1[j]);
                acc[2 * j]     += w0 * f0.x + w1 * f1.x;
                acc[2 * j + 1] += w0 * f0.y + w1 * f1.y;
            }
        } else {
            uint2 r0 = *(const uint2*)p0;
            uint2 r1 = *(const uint2*)p1;
            const __half2* v0 = (const __half2*)&r0;
            const __half2* v1 = (const __half2*)&r1;
            #pragma unroll
            for (int j = 0; j < 2; j++) {
                float2 f0 = __half22float2(v0[j]);
                float2 f1 = __half22float2(v1[j]);
                acc[2 * j]     += w0 * f0.x + w1 * f1.x;
                acc[2 * j + 1] += w0 * f0.y + w1 * f1.y;
            }
        }
    }
    if (e < end) {
        int   s = g_csr_src[e];
        float w = g_csr_w[e];
        const __half* sp = h + (size_t)s * F + lane * H;
        if (H == 8) {
            uint4 raw = *(const uint4*)sp;
            const __half2* v = (const __half2*)&raw;
            #pragma unroll
            for (int j = 0; j < 4; j++) {
                float2 f = __half22float2(v[j]);
                acc[2 * j]     += w * f.x;
                acc[2 * j + 1] += w * f.y;
            }
        } else {
            uint2 raw = *(const uint2*)sp;
            const __half2* v = (const __half2*)&raw;
            #pragma unroll
            for (int j = 0; j < 2; j++) {
                float2 f = __half22float2(v[j]);
                acc[2 * j]     += w * f.x;
                acc[2 * j + 1] += w * f.y;
            }
        }
    }

    const float* bp = bias + lane * H;
    float* op = out + (size_t)node * F + lane * H;
    #pragma unroll
    for (int j = 0; j < H / 4; j++) {
        float4 b = *(const float4*)(bp + 4 * j);
        float4 o = make_float4(acc[4 * j] + b.x,     acc[4 * j + 1] + b.y,
                               acc[4 * j + 2] + b.z, acc[4 * j + 3] + b.w);
        if (LAYER == 0) {
            o.x = fmaxf(o.x, 0.f); o.y = fmaxf(o.y, 0.f);
            o.z = fmaxf(o.z, 0.f); o.w = fmaxf(o.w, 0.f);
        }
        *(float4*)(op + 4 * j) = o;
    }
}

// ---------------------------------------------------------------------------
// launch — prep chain forked onto a second stream, joined before gather<0>
// ---------------------------------------------------------------------------
extern "C" void kernel_launch(void* const* d_in, const int* in_sizes, int n_in,
                              void* d_out, int out_size) {
    const float* x  = nullptr;
    const void*  ei = nullptr;
    const float* W1 = nullptr;
    const float* b1 = nullptr;
    const float* W2 = nullptr;
    const float* b2 = nullptr;

    for (int i = 0; i < n_in; i++) {
        switch (in_sizes[i]) {
            case NN * FIN:   x  = (const float*)d_in[i]; break;
            case 2 * NE:     ei = d_in[i];               break;
            case FIN * FH:   W1 = (const float*)d_in[i]; break;
            case FH:         b1 = (const float*)d_in[i]; break;
            case FH * FO:    W2 = (const float*)d_in[i]; break;
            case FO:         b2 = (const float*)d_in[i]; break;
            default: break;
        }
    }
    float* out = (float*)d_out;

    static cudaStream_t s2 = nullptr;
    static cudaEvent_t evFork = nullptr, evJoin = nullptr;
    if (s2 == nullptr) {
        cudaStreamCreateWithFlags(&s2, cudaStreamNonBlocking);
        cudaEventCreateWithFlags(&evFork, cudaEventDisableTiming);
        cudaEventCreateWithFlags(&evJoin, cudaEventDisableTiming);
        cudaFuncSetAttribute(mma_gemm,
                             cudaFuncAttributeMaxDynamicSharedMemorySize,
                             SMEM_TOTAL);
    }

    const int T = 256;
    const int NBLK = (NN + 255) / 256;

    // fork: prep chain + W2 convert on s2
    cudaEventRecord(evFork, 0);
    cudaStreamWaitEvent(s2, evFork, 0);

    k_detect   <<<1, 32, 0, s2>>>(ei);
    k_init     <<<(NN + T - 1) / T, T, 0, s2>>>();
    k_deg_count<<<(NE + T - 1) / T, T, 0, s2>>>(ei);
    k_dinv     <<<(NN + T - 1) / T, T, 0, s2>>>();
    k_scan1    <<<NBLK, 256, 0, s2>>>();
    k_scan2    <<<1, 256, 0, s2>>>(NBLK);
    k_scan3    <<<NBLK, 256, 0, s2>>>();
    k_fill     <<<(NE + T - 1) / T, T, 0, s2>>>(ei);
    k_conv_b   <<<(FH * FO + T - 1) / T, T, 0, s2>>>(W2, 1, FH, FO);

    // main stream: layer-1 GEMM
    k_conv_b<<<(FIN * FH + T - 1) / T, T>>>(W1, 0, FIN, FH);
    {
        dim3 grid(FH / 128, (NN + 127) / 128);
        mma_gemm<<<grid, 256, SMEM_TOTAL>>>(x, 0, NN, FH, FIN);
    }

    // join
    cudaEventRecord(evJoin, s2);
    cudaStreamWaitEvent(0, evJoin, 0);

    k_gather<0><<<((size_t)NN * 32 + T - 1) / T, T>>>(b1, nullptr);

    // layer 2
    {
        dim3 grid(FO / 128, (NN + 127) / 128);
        mma_gemm<<<grid, 256, SMEM_TOTAL>>>(nullptr, 1, NN, FO, FH);
    }
    k_gather<1><<<((size_t)NN * 32 + T - 1) / T, T>>>(b2, out);
}

// round 16
// speedup vs baseline: 2.8746x; 1.1891x over previous
#include <cuda_runtime.h>
#include <cuda_fp16.h>
#include <stdint.h>

#define NN  50000
#define NE  800000
#define FIN 512
#define FH  256
#define FO  128

// ---- scratch: __device__ globals ----
__device__ int   g_is64;
__device__ __align__(16) float g_dinv[NN];
__device__ __align__(16) int   g_cnt [NN];
__device__ __align__(16) int   g_off [NN + 1];
__device__ __align__(16) int   g_fill[NN];
__device__ __align__(16) int   g_blk [256];
__device__ __align__(16) int   g_csr_src[NE];
__device__ __align__(16) float g_csr_w  [NE];
__device__ __align__(16) __half g_h1  [(size_t)NN * FH];   // fp16 activations
__device__ __align__(16) float  g_agg1[(size_t)NN * FH];   // fp32 agg
__device__ __align__(16) __half g_h2  [(size_t)NN * FO];
__device__ __align__(16) __half g_Bh [(size_t)FH * FIN];   // W1^T fp16
__device__ __align__(16) __half g_Bh2[(size_t)FO * FH];    // W2^T fp16

// ---------------------------------------------------------------------------
// edge dtype detect (parallel) + decode
// ---------------------------------------------------------------------------
__global__ void k_detect(const void* __restrict__ ei) {
    const long long* p = (const long long*)ei;
    int lane = threadIdx.x;
    int bad = 0;
    #pragma unroll 4
    for (int i = lane; i < 2048; i += 32) {
        long long v = p[i];
        if (v < 0 || v >= NN) bad = 1;
    }
    unsigned m = __ballot_sync(0xffffffffu, bad);
    if (lane == 0) g_is64 = (m == 0);
}

__device__ __forceinline__ unsigned eidx(const void* __restrict__ ei, size_t idx) {
    if (g_is64) return (unsigned)((const long long*)ei)[idx];
    return (unsigned)((const int*)ei)[idx];
}

// ---------------------------------------------------------------------------
// degree / normalization / CSR build
// ---------------------------------------------------------------------------
__global__ void k_init() {
    int i = blockIdx.x * blockDim.x + threadIdx.x;
    if (i < NN) { g_cnt[i] = 0; g_fill[i] = 0; }
}

__global__ void k_deg_count(const void* __restrict__ ei) {
    int i = blockIdx.x * blockDim.x + threadIdx.x;
    if (i < NE) {
        unsigned d = eidx(ei, (size_t)NE + i);
        if (d < NN) atomicAdd(&g_cnt[d], 1);
    }
}

__global__ void k_dinv() {
    int i = blockIdx.x * blockDim.x + threadIdx.x;
    if (i < NN) g_dinv[i] = rsqrtf((float)(g_cnt[i] + 1));
}

__global__ void k_scan1() {
    __shared__ int wsum[8];
    int i = blockIdx.x * 256 + threadIdx.x;
    int lane = threadIdx.x & 31, wid = threadIdx.x >> 5;
    int v = (i < NN) ? g_cnt[i] : 0;
    int s = v;
    #pragma unroll
    for (int o = 1; o < 32; o <<= 1) {
        int t = __shfl_up_sync(0xffffffffu, s, o);
        if (lane >= o) s += t;
    }
    if (lane == 31) wsum[wid] = s;
    __syncthreads();
    if (wid == 0 && lane < 8) {
        int w = wsum[lane];
        #pragma unroll
        for (int o = 1; o < 8; o <<= 1) {
            int t = __shfl_up_sync(0xffu, w, o);
            if (lane >= o) w += t;
        }
        wsum[lane] = w;
    }
    __syncthreads();
    int woff = (wid == 0) ? 0 : wsum[wid - 1];
    if (i < NN) g_off[i] = woff + s - v;
    if (threadIdx.x == 255) g_blk[blockIdx.x] = woff + s;
}

__global__ void k_scan2(int nblk) {
    __shared__ int wsum[8];
    int lane = threadIdx.x & 31, wid = threadIdx.x >> 5;
    int v = (threadIdx.x < nblk) ? g_blk[threadIdx.x] : 0;
    int s = v;
    #pragma unroll
    for (int o = 1; o < 32; o <<= 1) {
        int t = __shfl_up_sync(0xffffffffu, s, o);
        if (lane >= o) s += t;
    }
    if (lane == 31) wsum[wid] = s;
    __syncthreads();
    if (wid == 0 && lane < 8) {
        int w = wsum[lane];
        #pragma unroll
        for (int o = 1; o < 8; o <<= 1) {
            int t = __shfl_up_sync(0xffu, w, o);
            if (lane >= o) w += t;
        }
        wsum[lane] = w;
    }
    __syncthreads();
    int woff = (wid == 0) ? 0 : wsum[wid - 1];
    if (threadIdx.x < nblk) g_blk[threadIdx.x] = woff + s - v;
    if (threadIdx.x == 255) g_off[NN] = woff + s;
}

__global__ void k_scan3() {
    int i = blockIdx.x * 256 + threadIdx.x;
    if (i < NN) g_off[i] += g_blk[i >> 8];
}

__global__ void k_fill(const void* __restrict__ ei) {
    int i = blockIdx.x * blockDim.x + threadIdx.x;
    if (i < NE) {
        unsigned s = eidx(ei, i);
        unsigned d = eidx(ei, (size_t)NE + i);
        if (s < NN && d < NN) {
            int pos = g_off[d] + atomicAdd(&g_fill[d], 1);
            if (pos < NE) {
                g_csr_src[pos] = (int)s;
                g_csr_w[pos]   = g_dinv[s] * g_dinv[d];
            }
        }
    }
}

// ---------------------------------------------------------------------------
// B convert: W [K][N] fp32 -> [N][K] fp16 (transposed); buffer per layer
// ---------------------------------------------------------------------------
__global__ void k_conv_b(const float* __restrict__ W, int layer, int K, int N) {
    __half* dst = (layer == 0) ? g_Bh : g_Bh2;
    int i = blockIdx.x * blockDim.x + threadIdx.x;
    if (i >= K * N) return;
    int k = i / N, n = i % N;
    dst[(size_t)n * K + k] = __float2half(W[i]);
}

// ---------------------------------------------------------------------------
// fp16 mma GEMM with cp.async double buffering; fp16 C output.
// C[M,N](fp16) = fp16(A[M,K]) @ B[N,K](fp16)^T, fp32 accum.
// ---------------------------------------------------------------------------
#define SRH 40
#define SRF 36
#define SZ_STAGEA (128 * SRF * 4)
#define SZ_HTILE  (128 * SRH * 2)
#define OFF_STAGEA 0
#define OFF_BS  (2 * SZ_STAGEA)
#define OFF_AH  (OFF_BS + 2 * SZ_HTILE)
#define SMEM_TOTAL (OFF_AH + 2 * SZ_HTILE)   // 77824

#define LDSM_X4(r0, r1, r2, r3, addr)                                        \
    asm volatile("ldmatrix.sync.aligned.m8n8.x4.shared.b16 {%0,%1,%2,%3}, [%4];" \
                 : "=r"(r0), "=r"(r1), "=r"(r2), "=r"(r3) : "r"(addr))

__device__ __forceinline__ void cp16(uint32_t dst, const void* src, int srcsz) {
    asm volatile("cp.async.cg.shared.global [%0], [%1], 16, %2;"
                 :: "r"(dst), "l"(src), "r"(srcsz));
}

__global__ void __launch_bounds__(256)
mma_gemm(const float* __restrict__ Aext, int layer, int M, int N, int K) {
    const float*  A = (layer == 0) ? Aext : (const float*)g_agg1;
    __half*       C = (layer == 0) ? g_h1 : g_h2;
    const __half* B = (layer == 0) ? g_Bh : g_Bh2;

    extern __shared__ __align__(16) char dyn[];
    const uint32_t sbase = (uint32_t)__cvta_generic_to_shared(dyn);

    const int tid  = threadIdx.x;
    const int lane = tid & 31;
    const int wid  = tid >> 5;
    const int wm   = wid >> 2;
    const int wn   = wid & 3;
    const int row0 = blockIdx.y * 128;
    const int col0 = blockIdx.x * 128;

    const int ldr = tid >> 1;
    const int ldc = (tid & 1) * 16;

    const int gm = row0 + ldr;
    const int gn = col0 + ldr;
    const int a_ok = (gm < M) ? 16 : 0;
    const float*  a_base = A + (size_t)gm * K + ldc;
    const __half* b_base = B + (size_t)gn * K + ldc;
    const uint32_t da = sbase + OFF_STAGEA + (uint32_t)((ldr * SRF + ldc) * 4);
    const uint32_t db = sbase + OFF_BS     + (uint32_t)((ldr * SRH + ldc) * 2);

    float acc[4][4][4];
    #pragma unroll
    for (int mi = 0; mi < 4; mi++)
        #pragma unroll
        for (int ni = 0; ni < 4; ni++)
            #pragma unroll
            for (int q = 0; q < 4; q++) acc[mi][ni][q] = 0.f;

    const int a_row  = (lane & 15);
    const int a_colh = (lane >> 4) * 8;
    const int b_row  = (lane >> 4) * 8 + (lane & 7);
    const int b_colh = ((lane >> 3) & 1) * 8;

    const int NC = K >> 5;

    {
        #pragma unroll
        for (int j = 0; j < 4; j++) cp16(da + j * 16, a_base + j * 4, a_ok);
        #pragma unroll
        for (int j = 0; j < 2; j++) cp16(db + j * 16, b_base + j * 8, 16);
        asm volatile("cp.async.commit_group;");
    }

    int buf = 0;
    for (int c = 0; c < NC; c++) {
        asm volatile("cp.async.wait_group 0;");
        __syncthreads();

        if (c + 1 < NC) {
            int k0 = (c + 1) * 32;
            uint32_t da2 = da + (buf ^ 1) * SZ_STAGEA;
            uint32_t db2 = db + (buf ^ 1) * SZ_HTILE;
            #pragma unroll
            for (int j = 0; j < 4; j++) cp16(da2 + j * 16, a_base + k0 + j * 4, a_ok);
            #pragma unroll
            for (int j = 0; j < 2; j++) cp16(db2 + j * 16, b_base + k0 + j * 8, 16);
            asm volatile("cp.async.commit_group;");
        }

        // convert stageA[buf] fp32 -> Ah[buf] fp16
        {
            const float4* src = (const float4*)(dyn + OFF_STAGEA + buf * SZ_STAGEA
                                                + (ldr * SRF + ldc) * 4);
            __half2* hh = (__half2*)(dyn + OFF_AH + buf * SZ_HTILE
                                     + (ldr * SRH + ldc) * 2);
            #pragma unroll
            for (int j = 0; j < 4; j++) {
                float4 v = src[j];
                hh[2 * j]     = __floats2half2_rn(v.x, v.y);
                hh[2 * j + 1] = __floats2half2_rn(v.z, v.w);
            }
        }
        __syncthreads();

        const uint32_t sAh = sbase + OFF_AH + buf * SZ_HTILE;
        const uint32_t sB  = sbase + OFF_BS + buf * SZ_HTILE;

        #pragma unroll
        for (int kk = 0; kk < 2; kk++) {
            const int kh = kk * 16;
            uint32_t bfr[4][2];
            #pragma unroll
            for (int nip = 0; nip < 2; nip++) {
                uint32_t addr = sB +
                    (uint32_t)(((wn * 32 + nip * 16 + b_row) * SRH + kh + b_colh) * 2);
                LDSM_X4(bfr[2 * nip][0], bfr[2 * nip][1],
                        bfr[2 * nip + 1][0], bfr[2 * nip + 1][1], addr);
            }
            uint32_t afr[4][4];
            #pragma unroll
            for (int mi = 0; mi < 4; mi++) {
                uint32_t addr = sAh +
                    (uint32_t)(((wm * 64 + mi * 16 + a_row) * SRH + kh + a_colh) * 2);
                LDSM_X4(afr[mi][0], afr[mi][1], afr[mi][2], afr[mi][3], addr);
            }
            #pragma unroll
            for (int mi = 0; mi < 4; mi++)
                #pragma unroll
                for (int ni = 0; ni < 4; ni++) {
                    asm volatile(
                        "mma.sync.aligned.m16n8k16.row.col.f32.f16.f16.f32 "
                        "{%0,%1,%2,%3}, {%4,%5,%6,%7}, {%8,%9}, {%0,%1,%2,%3};"
                        : "+f"(acc[mi][ni][0]), "+f"(acc[mi][ni][1]),
                          "+f"(acc[mi][ni][2]), "+f"(acc[mi][ni][3])
                        : "r"(afr[mi][0]), "r"(afr[mi][1]),
                          "r"(afr[mi][2]), "r"(afr[mi][3]),
                          "r"(bfr[ni][0]), "r"(bfr[ni][1]));
                }
        }
        buf ^= 1;
    }

    const int lr = lane >> 2, lc = lane & 3;
    #pragma unroll
    for (int mi = 0; mi < 4; mi++) {
        int r0 = row0 + wm * 64 + mi * 16 + lr;
        int r1 = r0 + 8;
        #pragma unroll
        for (int ni = 0; ni < 4; ni++) {
            int cb = col0 + wn * 32 + ni * 8 + lc * 2;
            if (r0 < M)
                *(__half2*)&C[(size_t)r0 * N + cb] =
                    __floats2half2_rn(acc[mi][ni][0], acc[mi][ni][1]);
            if (r1 < M)
                *(__half2*)&C[(size_t)r1 * N + cb] =
                    __floats2half2_rn(acc[mi][ni][2], acc[mi][ni][3]);
        }
    }
}

// ---------------------------------------------------------------------------
// CSR gather (fp16 h), edge loop unrolled x2.
// ---------------------------------------------------------------------------
template<int LAYER>
__global__ void k_gather(const float* __restrict__ bias,
                         float* __restrict__ outext) {
    constexpr int F = (LAYER == 0) ? FH : FO;
    constexpr int H = F / 32;
    const __half* h   = (LAYER == 0) ? (const __half*)g_h1 : (const __half*)g_h2;
    float*        out = (LAYER == 0) ? g_agg1 : outext;

    int node = (blockIdx.x * blockDim.x + threadIdx.x) >> 5;
    int lane = threadIdx.x & 31;
    if (node >= NN) return;

    float acc[H];
    float wi = g_dinv[node];
    wi *= wi;

    {
        const __half2* p = (const __half2*)(h + (size_t)node * F + lane * H);
        #pragma unroll
        for (int j = 0; j < H / 2; j++) {
            float2 f = __half22float2(p[j]);
            acc[2 * j]     = wi * f.x;
            acc[2 * j + 1] = wi * f.y;
        }
    }

    int beg = g_off[node];
    int end = beg + g_cnt[node];
    int e = beg;
    for (; e + 2 <= end; e += 2) {
        int   s0 = g_csr_src[e],     s1 = g_csr_src[e + 1];
        float w0 = g_csr_w[e],       w1 = g_csr_w[e + 1];
        const __half* p0 = h + (size_t)s0 * F + lane * H;
        const __half* p1 = h + (size_t)s1 * F + lane * H;
        if (H == 8) {
            uint4 r0 = *(const uint4*)p0;
            uint4 r1 = *(const uint4*)p1;
            const __half2* v0 = (const __half2*)&r0;
            const __half2* v1 = (const __half2*)&r1;
            #pragma unroll
            for (int j = 0; j < 4; j++) {
                float2 f0 = __half22float2(v0[j]);
                float2 f1 = __half22float2(v1[j]);
                acc[2 * j]     += w0 * f0.x + w1 * f1.x;
                acc[2 * j + 1] += w0 * f0.y + w1 * f1.y;
            }
        } else {
            uint2 r0 = *(const uint2*)p0;
            uint2 r1 = *(const uint2*)p1;
            const __half2* v0 = (const __half2*)&r0;
            const __half2* v1 = (const __half2*)&r1;
            #pragma unroll
            for (int j = 0; j < 2; j++) {
                float2 f0 = __half22float2(v0[j]);
                float2 f1 = __half22float2(v1[j]);
                acc[2 * j]     += w0 * f0.x + w1 * f1.x;
                acc[2 * j + 1] += w0 * f0.y + w1 * f1.y;
            }
        }
    }
    if (e < end) {
        int   s = g_csr_src[e];
        float w = g_csr_w[e];
        const __half* sp = h + (size_t)s * F + lane * H;
        if (H == 8) {
            uint4 raw = *(const uint4*)sp;
            const __half2* v = (const __half2*)&raw;
            #pragma unroll
            for (int j = 0; j < 4; j++) {
                float2 f = __half22float2(v[j]);
                acc[2 * j]     += w * f.x;
                acc[2 * j + 1] += w * f.y;
            }
        } else {
            uint2 raw = *(const uint2*)sp;
            const __half2* v = (const __half2*)&raw;
            #pragma unroll
            for (int j = 0; j < 2; j++) {
                float2 f = __half22float2(v[j]);
                acc[2 * j]     += w * f.x;
                acc[2 * j + 1] += w * f.y;
            }
        }
    }

    const float* bp = bias + lane * H;
    float* op = out + (size_t)node * F + lane * H;
    #pragma unroll
    for (int j = 0; j < H / 4; j++) {
        float4 b = *(const float4*)(bp + 4 * j);
        float4 o = make_float4(acc[4 * j] + b.x,     acc[4 * j + 1] + b.y,
                               acc[4 * j + 2] + b.z, acc[4 * j + 3] + b.w);
        if (LAYER == 0) {
            o.x = fmaxf(o.x, 0.f); o.y = fmaxf(o.y, 0.f);
            o.z = fmaxf(o.z, 0.f); o.w = fmaxf(o.w, 0.f);
        }
        *(float4*)(op + 4 * j) = o;
    }
}

// ---------------------------------------------------------------------------
// launch — prep chain forked onto a second stream, joined before gather<0>
// ---------------------------------------------------------------------------
extern "C" void kernel_launch(void* const* d_in, const int* in_sizes, int n_in,
                              void* d_out, int out_size) {
    const float* x  = nullptr;
    const void*  ei = nullptr;
    const float* W1 = nullptr;
    const float* b1 = nullptr;
    const float* W2 = nullptr;
    const float* b2 = nullptr;

    for (int i = 0; i < n_in; i++) {
        switch (in_sizes[i]) {
            case NN * FIN:   x  = (const float*)d_in[i]; break;
            case 2 * NE:     ei = d_in[i];               break;
            case FIN * FH:   W1 = (const float*)d_in[i]; break;
            case FH:         b1 = (const float*)d_in[i]; break;
            case FH * FO:    W2 = (const float*)d_in[i]; break;
            case FO:         b2 = (const float*)d_in[i]; break;
            default: break;
        }
    }
    float* out = (float*)d_out;

    static cudaStream_t s2 = nullptr;
    static cudaEvent_t evFork = nullptr, evJoin = nullptr;
    if (s2 == nullptr) {
        cudaStreamCreateWithFlags(&s2, cudaStreamNonBlocking);
        cudaEventCreateWithFlags(&evFork, cudaEventDisableTiming);
        cudaEventCreateWithFlags(&evJoin, cudaEventDisableTiming);
        cudaFuncSetAttribute(mma_gemm,
                             cudaFuncAttributeMaxDynamicSharedMemorySize,
                             SMEM_TOTAL);
    }

    const int T = 256;
    const int NBLK = (NN + 255) / 256;

    // fork: prep chain + W2 convert on s2
    cudaEventRecord(evFork, 0);
    cudaStreamWaitEvent(s2, evFork, 0);

    k_detect   <<<1, 32, 0, s2>>>(ei);
    k_init     <<<(NN + T - 1) / T, T, 0, s2>>>();
    k_deg_count<<<(NE + T - 1) / T, T, 0, s2>>>(ei);
    k_dinv     <<<(NN + T - 1) / T, T, 0, s2>>>();
    k_scan1    <<<NBLK, 256, 0, s2>>>();
    k_scan2    <<<1, 256, 0, s2>>>(NBLK);
    k_scan3    <<<NBLK, 256, 0, s2>>>();
    k_fill     <<<(NE + T - 1) / T, T, 0, s2>>>(ei);
    k_conv_b   <<<(FH * FO + T - 1) / T, T, 0, s2>>>(W2, 1, FH, FO);

    // main stream: layer-1 GEMM
    k_conv_b<<<(FIN * FH + T - 1) / T, T>>>(W1, 0, FIN, FH);
    {
        dim3 grid(FH / 128, (NN + 127) / 128);
        mma_gemm<<<grid, 256, SMEM_TOTAL>>>(x, 0, NN, FH, FIN);
    }

    // join
    cudaEventRecord(evJoin, s2);
    cudaStreamWaitEvent(0, evJoin, 0);

    k_gather<0><<<((size_t)NN * 32 + T - 1) / T, T>>>(b1, nullptr);

    // layer 2
    {
        dim3 grid(FO / 128, (NN + 127) / 128);
        mma_gemm<<<grid, 256, SMEM_TOTAL>>>(nullptr, 1, NN, FO, FH);
    }
    k_gather<1><<<((size_t)NN * 32 + T - 1) / T, T>>>(b2, out);
}

// round 17
// speedup vs baseline: 3.1216x; 1.0859x over previous
#include <cuda_runtime.h>
#include <cuda_fp16.h>
#include <stdint.h>

#define NN  50000
#define NE  800000
#define FIN 512
#define FH  256
#define FO  128

// ---- scratch: __device__ globals ----
__device__ int   g_is64;
__device__ __align__(16) float  g_dinv[NN];
__device__ __align__(16) int    g_cnt [NN];
__device__ __align__(16) int    g_off [NN + 1];
__device__ __align__(16) int    g_fill[NN];
__device__ __align__(16) int    g_blk [256];
__device__ __align__(16) int    g_csr_src[NE];
__device__ __align__(16) float  g_csr_w  [NE];
__device__ __align__(16) __half g_xh  [(size_t)NN * FIN];  // x in fp16
__device__ __align__(16) __half g_h1  [(size_t)NN * FH];   // fp16 activations
__device__ __align__(16) __half g_agg1[(size_t)NN * FH];   // fp16 agg (GEMM2 rounds anyway)
__device__ __align__(16) __half g_h2  [(size_t)NN * FO];
__device__ __align__(16) __half g_Bh [(size_t)FH * FIN];   // W1^T fp16
__device__ __align__(16) __half g_Bh2[(size_t)FO * FH];    // W2^T fp16

// ---------------------------------------------------------------------------
// edge dtype detect (parallel) + decode
// ---------------------------------------------------------------------------
__global__ void k_detect(const void* __restrict__ ei) {
    const long long* p = (const long long*)ei;
    int lane = threadIdx.x;
    int bad = 0;
    #pragma unroll 4
    for (int i = lane; i < 2048; i += 32) {
        long long v = p[i];
        if (v < 0 || v >= NN) bad = 1;
    }
    unsigned m = __ballot_sync(0xffffffffu, bad);
    if (lane == 0) g_is64 = (m == 0);
}

__device__ __forceinline__ unsigned eidx(const void* __restrict__ ei, size_t idx) {
    if (g_is64) return (unsigned)((const long long*)ei)[idx];
    return (unsigned)((const int*)ei)[idx];
}

// ---------------------------------------------------------------------------
// degree / normalization / CSR build
// ---------------------------------------------------------------------------
__global__ void k_init() {
    int i = blockIdx.x * blockDim.x + threadIdx.x;
    if (i < NN) { g_cnt[i] = 0; g_fill[i] = 0; }
}

__global__ void k_deg_count(const void* __restrict__ ei) {
    int i = blockIdx.x * blockDim.x + threadIdx.x;
    if (i < NE) {
        unsigned d = eidx(ei, (size_t)NE + i);
        if (d < NN) atomicAdd(&g_cnt[d], 1);
    }
}

__global__ void k_dinv() {
    int i = blockIdx.x * blockDim.x + threadIdx.x;
    if (i < NN) g_dinv[i] = rsqrtf((float)(g_cnt[i] + 1));
}

__global__ void k_scan1() {
    __shared__ int wsum[8];
    int i = blockIdx.x * 256 + threadIdx.x;
    int lane = threadIdx.x & 31, wid = threadIdx.x >> 5;
    int v = (i < NN) ? g_cnt[i] : 0;
    int s = v;
    #pragma unroll
    for (int o = 1; o < 32; o <<= 1) {
        int t = __shfl_up_sync(0xffffffffu, s, o);
        if (lane >= o) s += t;
    }
    if (lane == 31) wsum[wid] = s;
    __syncthreads();
    if (wid == 0 && lane < 8) {
        int w = wsum[lane];
        #pragma unroll
        for (int o = 1; o < 8; o <<= 1) {
            int t = __shfl_up_sync(0xffu, w, o);
            if (lane >= o) w += t;
        }
        wsum[lane] = w;
    }
    __syncthreads();
    int woff = (wid == 0) ? 0 : wsum[wid - 1];
    if (i < NN) g_off[i] = woff + s - v;
    if (threadIdx.x == 255) g_blk[blockIdx.x] = woff + s;
}

__global__ void k_scan2(int nblk) {
    __shared__ int wsum[8];
    int lane = threadIdx.x & 31, wid = threadIdx.x >> 5;
    int v = (threadIdx.x < nblk) ? g_blk[threadIdx.x] : 0;
    int s = v;
    #pragma unroll
    for (int o = 1; o < 32; o <<= 1) {
        int t = __shfl_up_sync(0xffffffffu, s, o);
        if (lane >= o) s += t;
    }
    if (lane == 31) wsum[wid] = s;
    __syncthreads();
    if (wid == 0 && lane < 8) {
        int w = wsum[lane];
        #pragma unroll
        for (int o = 1; o < 8; o <<= 1) {
            int t = __shfl_up_sync(0xffu, w, o);
            if (lane >= o) w += t;
        }
        wsum[lane] = w;
    }
    __syncthreads();
    int woff = (wid == 0) ? 0 : wsum[wid - 1];
    if (threadIdx.x < nblk) g_blk[threadIdx.x] = woff + s - v;
    if (threadIdx.x == 255) g_off[NN] = woff + s;
}

__global__ void k_scan3() {
    int i = blockIdx.x * 256 + threadIdx.x;
    if (i < NN) g_off[i] += g_blk[i >> 8];
}

__global__ void k_fill(const void* __restrict__ ei) {
    int i = blockIdx.x * blockDim.x + threadIdx.x;
    if (i < NE) {
        unsigned s = eidx(ei, i);
        unsigned d = eidx(ei, (size_t)NE + i);
        if (s < NN && d < NN) {
            int pos = g_off[d] + atomicAdd(&g_fill[d], 1);
            if (pos < NE) {
                g_csr_src[pos] = (int)s;
                g_csr_w[pos]   = g_dinv[s] * g_dinv[d];
            }
        }
    }
}

// ---------------------------------------------------------------------------
// converts
// ---------------------------------------------------------------------------
__global__ void k_conv_b(const float* __restrict__ W, int layer, int K, int N) {
    __half* dst = (layer == 0) ? g_Bh : g_Bh2;
    int i = blockIdx.x * blockDim.x + threadIdx.x;
    if (i >= K * N) return;
    int k = i / N, n = i % N;
    dst[(size_t)n * K + k] = __float2half(W[i]);
}

__global__ void k_conv_x(const float* __restrict__ x) {
    size_t i = ((size_t)blockIdx.x * blockDim.x + threadIdx.x) * 4;
    if (i >= (size_t)NN * FIN) return;
    float4 v = *(const float4*)(x + i);
    __half2* d = (__half2*)(g_xh + i);
    d[0] = __floats2half2_rn(v.x, v.y);
    d[1] = __floats2half2_rn(v.z, v.w);
}

// ---------------------------------------------------------------------------
// fp16 mma GEMM, cp.async double buffering, NO conversion stage.
// C[M,N](fp16) = A[M,K](fp16) @ B[N,K](fp16)^T, fp32 accum.
// BM=BN=128, BK=32, 256 thr = 8 warps (2m x 4n). Static smem 40KB.
// layer 0: A=g_xh, B=g_Bh,  C=g_h1 ;  layer 1: A=g_agg1, B=g_Bh2, C=g_h2
// ---------------------------------------------------------------------------
#define SRH 40
#define SZ_HTILE (128 * SRH * 2)    // 10240 B

#define LDSM_X4(r0, r1, r2, r3, addr)                                        \
    asm volatile("ldmatrix.sync.aligned.m8n8.x4.shared.b16 {%0,%1,%2,%3}, [%4];" \
                 : "=r"(r0), "=r"(r1), "=r"(r2), "=r"(r3) : "r"(addr))

__device__ __forceinline__ void cp16(uint32_t dst, const void* src, int srcsz) {
    asm volatile("cp.async.cg.shared.global [%0], [%1], 16, %2;"
                 :: "r"(dst), "l"(src), "r"(srcsz));
}

__global__ void __launch_bounds__(256)
mma_gemm(int layer, int M, int N, int K) {
    const __half* A = (layer == 0) ? g_xh : g_agg1;
    const __half* B = (layer == 0) ? g_Bh : g_Bh2;
    __half*       C = (layer == 0) ? g_h1 : g_h2;

    __shared__ __align__(16) __half Atile[2][128 * SRH];
    __shared__ __align__(16) __half Btile[2][128 * SRH];
    const uint32_t sA0 = (uint32_t)__cvta_generic_to_shared(&Atile[0][0]);
    const uint32_t sB0 = (uint32_t)__cvta_generic_to_shared(&Btile[0][0]);

    const int tid  = threadIdx.x;
    const int lane = tid & 31;
    const int wid  = tid >> 5;
    const int wm   = wid >> 2;
    const int wn   = wid & 3;
    const int row0 = blockIdx.y * 128;
    const int col0 = blockIdx.x * 128;

    // tile-load coords: 2 x 16B per thread per tile (r 0..127, 8-half col chunk)
    const int t_r0 = tid >> 1;                 // iter 0 row
    const int t_c0 = (tid & 1) * 16;           // halls... 0 or 16
    // iteration i: idx = tid + i*256 -> r = idx>>1? No: 256 thr x 2 iters x 8 halfs
    // = 4096 halfs = 128 x 32. Use idx>>2? 16B = 8 halfs: 512 chunks of 8.
    // chunk id = tid + i*256 (0..511); r = id>>2, c = (id&3)*8.

    float acc[4][4][4];
    #pragma unroll
    for (int mi = 0; mi < 4; mi++)
        #pragma unroll
        for (int ni = 0; ni < 4; ni++)
            #pragma unroll
            for (int q = 0; q < 4; q++) acc[mi][ni][q] = 0.f;

    const int a_row  = (lane & 15);
    const int a_colh = (lane >> 4) * 8;
    const int b_row  = (lane >> 4) * 8 + (lane & 7);
    const int b_colh = ((lane >> 3) & 1) * 8;

    const int NC = K >> 5;

    auto issue_tiles = [&](int c, int buf) {
        int k0 = c * 32;
        #pragma unroll
        for (int i = 0; i < 2; i++) {
            int id = tid + i * 256;            // 0..511
            int r  = id >> 2;                  // 0..127
            int cc = (id & 3) * 8;             // 0,8,16,24
            int gm = row0 + r;
            cp16(sA0 + buf * SZ_HTILE + (uint32_t)((r * SRH + cc) * 2),
                 A + (size_t)gm * K + k0 + cc, gm < M ? 16 : 0);
            int gn = col0 + r;                 // N multiple of 128
            cp16(sB0 + buf * SZ_HTILE + (uint32_t)((r * SRH + cc) * 2),
                 B + (size_t)gn * K + k0 + cc, 16);
        }
        asm volatile("cp.async.commit_group;");
    };

    issue_tiles(0, 0);

    int buf = 0;
    for (int c = 0; c < NC; c++) {
        if (c + 1 < NC) {
            issue_tiles(c + 1, buf ^ 1);
            asm volatile("cp.async.wait_group 1;");
        } else {
            asm volatile("cp.async.wait_group 0;");
        }
        __syncthreads();

        const uint32_t sA = sA0 + buf * SZ_HTILE;
        const uint32_t sB = sB0 + buf * SZ_HTILE;

        #pragma unroll
        for (int kk = 0; kk < 2; kk++) {
            const int kh = kk * 16;
            uint32_t bfr[4][2];
            #pragma unroll
            for (int nip = 0; nip < 2; nip++) {
                uint32_t addr = sB +
                    (uint32_t)(((wn * 32 + nip * 16 + b_row) * SRH + kh + b_colh) * 2);
                LDSM_X4(bfr[2 * nip][0], bfr[2 * nip][1],
                        bfr[2 * nip + 1][0], bfr[2 * nip + 1][1], addr);
            }
            uint32_t afr[4][4];
            #pragma unroll
            for (int mi = 0; mi < 4; mi++) {
                uint32_t addr = sA +
                    (uint32_t)(((wm * 64 + mi * 16 + a_row) * SRH + kh + a_colh) * 2);
                LDSM_X4(afr[mi][0], afr[mi][1], afr[mi][2], afr[mi][3], addr);
            }
            #pragma unroll
            for (int mi = 0; mi < 4; mi++)
                #pragma unroll
                for (int ni = 0; ni < 4; ni++) {
                    asm volatile(
                        "mma.sync.aligned.m16n8k16.row.col.f32.f16.f16.f32 "
                        "{%0,%1,%2,%3}, {%4,%5,%6,%7}, {%8,%9}, {%0,%1,%2,%3};"
                        : "+f"(acc[mi][ni][0]), "+f"(acc[mi][ni][1]),
                          "+f"(acc[mi][ni][2]), "+f"(acc[mi][ni][3])
                        : "r"(afr[mi][0]), "r"(afr[mi][1]),
                          "r"(afr[mi][2]), "r"(afr[mi][3]),
                          "r"(bfr[ni][0]), "r"(bfr[ni][1]));
                }
        }
        __syncthreads();   // all warps done with buf before it is overwritten
        buf ^= 1;
    }

    const int lr = lane >> 2, lc = lane & 3;
    #pragma unroll
    for (int mi = 0; mi < 4; mi++) {
        int r0 = row0 + wm * 64 + mi * 16 + lr;
        int r1 = r0 + 8;
        #pragma unroll
        for (int ni = 0; ni < 4; ni++) {
            int cb = col0 + wn * 32 + ni * 8 + lc * 2;
            if (r0 < M)
                *(__half2*)&C[(size_t)r0 * N + cb] =
                    __floats2half2_rn(acc[mi][ni][0], acc[mi][ni][1]);
            if (r1 < M)
                *(__half2*)&C[(size_t)r1 * N + cb] =
                    __floats2half2_rn(acc[mi][ni][2], acc[mi][ni][3]);
        }
    }
}

// ---------------------------------------------------------------------------
// CSR gather (fp16 h), edge loop unrolled x2.
// LAYER 0: out = g_agg1 (fp16) + ReLU ;  LAYER 1: out = d_out (fp32)
// ---------------------------------------------------------------------------
template<int LAYER>
__global__ void k_gather(const float* __restrict__ bias,
                         float* __restrict__ outext) {
    constexpr int F = (LAYER == 0) ? FH : FO;
    constexpr int H = F / 32;
    const __half* h = (LAYER == 0) ? (const __half*)g_h1 : (const __half*)g_h2;

    int node = (blockIdx.x * blockDim.x + threadIdx.x) >> 5;
    int lane = threadIdx.x & 31;
    if (node >= NN) return;

    float acc[H];
    float wi = g_dinv[node];
    wi *= wi;

    {
        const __half2* p = (const __half2*)(h + (size_t)node * F + lane * H);
        #pragma unroll
        for (int j = 0; j < H / 2; j++) {
            float2 f = __half22float2(p[j]);
            acc[2 * j]     = wi * f.x;
            acc[2 * j + 1] = wi * f.y;
        }
    }

    int beg = g_off[node];
    int end = beg + g_cnt[node];
    int e = beg;
    for (; e + 2 <= end; e += 2) {
        int   s0 = g_csr_src[e],     s1 = g_csr_src[e + 1];
        float w0 = g_csr_w[e],       w1 = g_csr_w[e + 1];
        const __half* p0 = h + (size_t)s0 * F + lane * H;
        const __half* p1 = h + (size_t)s1 * F + lane * H;
        if (H == 8) {
            uint4 r0 = *(const uint4*)p0;
            uint4 r1 = *(const uint4*)p1;
            const __half2* v0 = (const __half2*)&r0;
            const __half2* v1 = (const __half2*)&r1;
            #pragma unroll
            for (int j = 0; j < 4; j++) {
                float2 f0 = __half22float2(v0[j]);
                float2 f1 = __half22float2(v1[j]);
                acc[2 * j]     += w0 * f0.x + w1 * f1.x;
                acc[2 * j + 1] += w0 * f0.y + w1 * f1.y;
            }
        } else {
            uint2 r0 = *(const uint2*)p0;
            uint2 r1 = *(const uint2*)p1;
            const __half2* v0 = (const __half2*)&r0;
            const __half2* v1 = (const __half2*)&r1;
            #pragma unroll
            for (int j = 0; j < 2; j++) {
                float2 f0 = __half22float2(v0[j]);
                float2 f1 = __half22float2(v1[j]);
                acc[2 * j]     += w0 * f0.x + w1 * f1.x;
                acc[2 * j + 1] += w0 * f0.y + w1 * f1.y;
            }
        }
    }
    if (e < end) {
        int   s = g_csr_src[e];
        float w = g_csr_w[e];
        const __half* sp = h + (size_t)s * F + lane * H;
        if (H == 8) {
            uint4 raw = *(const uint4*)sp;
            const __half2* v = (const __half2*)&raw;
            #pragma unroll
            for (int j = 0; j < 4; j++) {
                float2 f = __half22float2(v[j]);
                acc[2 * j]     += w * f.x;
                acc[2 * j + 1] += w * f.y;
            }
        } else {
            uint2 raw = *(const uint2*)sp;
            const __half2* v = (const __half2*)&raw;
            #pragma unroll
            for (int j = 0; j < 2; j++) {
                float2 f = __half22float2(v[j]);
                acc[2 * j]     += w * f.x;
                acc[2 * j + 1] += w * f.y;
            }
        }
    }

    const float* bp = bias + lane * H;
    if (LAYER == 0) {
        __half2* op = (__half2*)(g_agg1 + (size_t)node * F + lane * H);
        #pragma unroll
        for (int j = 0; j < H / 2; j++) {
            float2 b = *(const float2*)(bp + 2 * j);
            float ox = fmaxf(acc[2 * j] + b.x, 0.f);
            float oy = fmaxf(acc[2 * j + 1] + b.y, 0.f);
            op[j] = __floats2half2_rn(ox, oy);
        }
    } else {
        float* op = outext + (size_t)node * F + lane * H;
        #pragma unroll
        for (int j = 0; j < H / 4; j++) {
            float4 b = *(const float4*)(bp + 4 * j);
            float4 o = make_float4(acc[4 * j] + b.x,     acc[4 * j + 1] + b.y,
                                   acc[4 * j + 2] + b.z, acc[4 * j + 3] + b.w);
            *(float4*)(op + 4 * j) = o;
        }
    }
}

// ---------------------------------------------------------------------------
// launch — prep chain forked onto a second stream, joined before gather<0>
// ---------------------------------------------------------------------------
extern "C" void kernel_launch(void* const* d_in, const int* in_sizes, int n_in,
                              void* d_out, int out_size) {
    const float* x  = nullptr;
    const void*  ei = nullptr;
    const float* W1 = nullptr;
    const float* b1 = nullptr;
    const float* W2 = nullptr;
    const float* b2 = nullptr;

    for (int i = 0; i < n_in; i++) {
        switch (in_sizes[i]) {
            case NN * FIN:   x  = (const float*)d_in[i]; break;
            case 2 * NE:     ei = d_in[i];               break;
            case FIN * FH:   W1 = (const float*)d_in[i]; break;
            case FH:         b1 = (const float*)d_in[i]; break;
            case FH * FO:    W2 = (const float*)d_in[i]; break;
            case FO:         b2 = (const float*)d_in[i]; break;
            default: break;
        }
    }
    float* out = (float*)d_out;

    static cudaStream_t s2 = nullptr;
    static cudaEvent_t evFork = nullptr, evJoin = nullptr;
    if (s2 == nullptr) {
        cudaStreamCreateWithFlags(&s2, cudaStreamNonBlocking);
        cudaEventCreateWithFlags(&evFork, cudaEventDisableTiming);
        cudaEventCreateWithFlags(&evJoin, cudaEventDisableTiming);
    }

    const int T = 256;
    const int NBLK = (NN + 255) / 256;

    // fork: prep chain + W2 convert on s2
    cudaEventRecord(evFork, 0);
    cudaStreamWaitEvent(s2, evFork, 0);

    k_detect   <<<1, 32, 0, s2>>>(ei);
    k_init     <<<(NN + T - 1) / T, T, 0, s2>>>();
    k_deg_count<<<(NE + T - 1) / T, T, 0, s2>>>(ei);
    k_dinv     <<<(NN + T - 1) / T, T, 0, s2>>>();
    k_scan1    <<<NBLK, 256, 0, s2>>>();
    k_scan2    <<<1, 256, 0, s2>>>(NBLK);
    k_scan3    <<<NBLK, 256, 0, s2>>>();
    k_fill     <<<(NE + T - 1) / T, T, 0, s2>>>(ei);
    k_conv_b   <<<(FH * FO + T - 1) / T, T, 0, s2>>>(W2, 1, FH, FO);

    // main stream: conversions + layer-1 GEMM
    k_conv_b<<<(FIN * FH + T - 1) / T, T>>>(W1, 0, FIN, FH);
    k_conv_x<<<(int)(((size_t)NN * FIN / 4 + T - 1) / T), T>>>(x);
    {
        dim3 grid(FH / 128, (NN + 127) / 128);
        mma_gemm<<<grid, 256>>>(0, NN, FH, FIN);
    }

    // join
    cudaEventRecord(evJoin, s2);
    cudaStreamWaitEvent(0, evJoin, 0);

    k_gather<0><<<((size_t)NN * 32 + T - 1) / T, T>>>(b1, nullptr);

    // layer 2
    {
        dim3 grid(FO / 128, (NN + 127) / 128);
        mma_gemm<<<grid, 256>>>(1, NN, FO, FH);
    }
    k_gather<1><<<((size_t)NN * 32 + T - 1) / T, T>>>(b2, out);
}